// round 13
// baseline (speedup 1.0000x reference)
#include <cuda_runtime.h>
#include <cuda_bf16.h>
#include <cstdint>

constexpr int cN  = 16, cL = 256, cS = 128, cE = 128, cA = 9;
constexpr int cD  = 768, cNH = 768, cIDXW = 130, cROLES = 24;
constexpr int cM  = cN * cA;            // 144
constexpr int SZS = 256 * cNH;          // padded slice rows

// ---------------- scratch ---------------------------------------------------
__device__ float g_sent   [cN * cS * cD];
__device__ float g_argraw [cN * cA * cD];
__device__ float g_argemb [cN * cA * cD];
__device__ float g_u2u    [cN * cA * cD];
__device__ float g_t2t    [cN * cS * cS];
__device__ float g_ent    [cN * cE * cD];
__device__ float g_X      [cN * cE * cS];
__device__ float g_w      [cN * cE * cA];
__device__ float g_Epart  [cN * cE * cNH];
__device__ float g_Epart2 [cN * cE * cNH];
__device__ float g_S4     [3 * SZS];       // argemb@W1, u2u@W5, argemb@W2 (padded)
__device__ float g_AtokW4 [cM * cNH];
__device__ __nv_bfloat16 g_Atil [2 * cN * cE * cD];  // tiled bf16 {ent, Ah2h}
__device__ __nv_bfloat16 g_Atil4[3 * 256 * cD];      // tiled bf16 {argemb, u2u, atok}
__device__ __nv_bfloat16 g_Btil [6 * cNH * cD];      // tiled bf16 W {0,3,4,1,5,2}

// ---------------- helpers ---------------------------------------------------
__device__ __forceinline__ void fma2(float2& d, float2 a, float2 b) {
    asm("fma.rn.f32x2 %0, %1, %2, %0;"
        : "+l"(reinterpret_cast<unsigned long long&>(d))
        : "l"(reinterpret_cast<unsigned long long&>(a)),
          "l"(reinterpret_cast<unsigned long long&>(b)));
}
__device__ __forceinline__ uint32_t smem_u32(const void* p) {
    return (uint32_t)__cvta_generic_to_shared(p);
}
__device__ __forceinline__ uint32_t pkbf(float a, float b) {
    __nv_bfloat162 h = __floats2bfloat162_rn(a, b);
    return *reinterpret_cast<uint32_t*>(&h);
}
__device__ __forceinline__ void ldsm4(uint32_t* r, uint32_t addr) {
    asm volatile("ldmatrix.sync.aligned.m8n8.x4.shared.b16 {%0,%1,%2,%3}, [%4];"
        : "=r"(r[0]), "=r"(r[1]), "=r"(r[2]), "=r"(r[3]) : "r"(addr));
}
__device__ __forceinline__ void mma16816(float* c, const uint32_t* a,
                                         uint32_t b0, uint32_t b1) {
    asm volatile(
        "mma.sync.aligned.m16n8k16.row.col.f32.bf16.bf16.f32 "
        "{%0,%1,%2,%3}, {%4,%5,%6,%7}, {%8,%9}, {%0,%1,%2,%3};"
        : "+f"(c[0]), "+f"(c[1]), "+f"(c[2]), "+f"(c[3])
        : "r"(a[0]), "r"(a[1]), "r"(a[2]), "r"(a[3]), "r"(b0), "r"(b1));
}
__device__ __forceinline__ void mbar_wait(uint32_t mbar, uint32_t parity) {
    uint32_t done;
    asm volatile("{\n\t.reg .pred p;\n\t"
        "mbarrier.try_wait.parity.acquire.cta.shared::cta.b64 p, [%1], %2;\n\t"
        "selp.b32 %0, 1, 0, p;\n\t}" : "=r"(done) : "r"(mbar), "r"(parity) : "memory");
    while (!done)
        asm volatile("{\n\t.reg .pred p;\n\t"
            "mbarrier.try_wait.parity.acquire.cta.shared::cta.b64 p, [%1], %2, 0x989680;\n\t"
            "selp.b32 %0, 1, 0, p;\n\t}" : "=r"(done) : "r"(mbar), "r"(parity) : "memory");
}

// ======================= role device functions ==============================

// ---- gather ----
__device__ void dev_gather(int row, const float* __restrict__ emb,
                           const int* __restrict__ idxs) {
    int tid = threadIdx.x;
    if (tid >= 192) return;
    if (row < cN * cS) {
        int n = row >> 7, s = row & 127;
        int src = idxs[n * cIDXW + s];
        ((float4*)(g_sent + (long)row * cD))[tid] =
            ((const float4*)(emb + ((long)n * cL + src) * cD))[tid];
    } else {
        int r = row - cN * cS, n = r / cA, a = r % cA;
        int src = idxs[n * cIDXW + cS] + 1 + a;
        ((float4*)(g_argraw + (long)r * cD))[tid] =
            ((const float4*)(emb + ((long)n * cL + src) * cD))[tid];
    }
}

// ---- t2t ----
__device__ void dev_t2t(char* sm, int bid, const float* __restrict__ attn,
                        const int* __restrict__ idxs) {
    float* rows = (float*)sm;                    // 36*256
    int*   sc   = (int*)(sm + 36864);
    float* r0   = (float*)(sm + 37376);
    float* r1   = (float*)(sm + 37888);
    float* r2   = (float*)(sm + 38400);
    int n = bid >> 7, a = bid & 127;
    int tid = threadIdx.x;
    if (tid < cS) sc[tid] = idxs[n * cIDXW + tid];
    __syncthreads();
    int i = sc[a];
    for (int idx = tid; idx < 36 * 64; idx += 256) {
        int r = idx >> 6, c = idx & 63;
        int l = r / 12, h = r - l * 12;
        long off = ((((long)l * cN + n) * 12 + h) * cL + i) * cL;
        *(float4*)&rows[r * 256 + c * 4] = *(const float4*)(attn + off + c * 4);
    }
    __syncthreads();
    float a0 = 0.f, a1 = 0.f, a2 = 0.f;
    if (tid < cS) {
        int j = sc[tid];
#pragma unroll
        for (int h = 0; h < 12; ++h) {
            a0 += rows[h * 256 + j];
            a1 += rows[(12 + h) * 256 + j];
            a2 += rows[(24 + h) * 256 + j];
        }
        r0[tid] = a0; r1[tid] = a1; r2[tid] = a2;
    }
    __syncthreads();
    for (int st = 64; st > 0; st >>= 1) {
        if (tid < st) { r0[tid] += r0[tid + st]; r1[tid] += r1[tid + st]; r2[tid] += r2[tid + st]; }
        __syncthreads();
    }
    if (tid < cS) {
        float d0 = r0[0] * (1.f / 12.f) + 1e-9f;
        float d1 = r1[0] * (1.f / 12.f) + 1e-9f;
        float d2 = r2[0] * (1.f / 12.f) + 1e-9f;
        g_t2t[((long)(n * cS + a)) * cS + tid] =
            ((a0 * (1.f / 12.f)) / d0 + (a1 * (1.f / 12.f)) / d1 +
             (a2 * (1.f / 12.f)) / d2) * (1.f / 3.f);
    }
}

// ---- convW: W1 blocks {0,3,4,1,5,2} -> tiled swizzled bf16 ----
__device__ void dev_convW(char* sm, int bid, const float* __restrict__ W1) {
    float (*tile)[33] = (float(*)[33])sm;
    int bx = bid % 24, by = (bid / 24) % 24, blk = bid / 576;  // 0..5
    const int map[6] = {0, 3, 4, 1, 5, 2};
    int wb = map[blk];
    int tid = threadIdx.x, tx = tid & 31, ty = tid >> 5;
    const float* src = W1 + (long)wb * cD * cNH;
    int k0 = by * 32, n0 = bx * 32;
#pragma unroll
    for (int j = 0; j < 4; ++j)
        tile[ty + j * 8][tx] = src[(long)(k0 + ty + j * 8) * cNH + n0 + tx];
    __syncthreads();
#pragma unroll
    for (int j = 0; j < 4; ++j) {
        int nIdx = n0 + ty + j * 8, kIdx = k0 + tx;
        long off = (((long)(blk * 6 + (nIdx >> 7)) * 12 + (kIdx >> 6)) * 128 +
                    (nIdx & 127)) * 128 +
                   (((kIdx & 63) * 2) ^ ((nIdx & 7) << 4));
        *(__nv_bfloat16*)((char*)g_Btil + off) = __float2bfloat16_rn(tile[tx][ty + j * 8]);
    }
}

// ---- argsmall (+ bf16 tiled argemb/u2u) ----
__device__ __forceinline__ void st_a4(int chunk, int m, int d, float v) {
    int mt = m >> 7, r = m & 127;
    long off = (((long)(chunk * 2 + mt) * 12 + (d >> 6)) * 128 + r) * 128 +
               (((d & 63) * 2) ^ ((r & 7) << 4));
    *(__nv_bfloat16*)((char*)g_Atil4 + off) = __float2bfloat16_rn(v);
}
__device__ void dev_argsmall(char* sm, int n, const float* __restrict__ argw) {
    float* s_ae  = (float*)sm;
    float* s_aw  = (float*)(sm + 27648);
    float* s_dot = (float*)(sm + 27984);
    float* s_a2a = (float*)(sm + 28320);
    int tid = threadIdx.x;
    if (tid < cA * cA) s_aw[tid] = argw[n * cA * cA + tid];
    __syncthreads();
    for (int idx = tid; idx < cA * cD; idx += 256) {
        int a = idx / cD, d = idx % cD;
        float acc = 0.f;
#pragma unroll
        for (int k = 0; k < cA; ++k)
            acc += g_argraw[((long)(n * cA + k)) * cD + d] * s_aw[k * cA + a];
        s_ae[a * cD + d] = acc;
        g_argemb[((long)(n * cA + a)) * cD + d] = acc;
        st_a4(0, n * cA + a, d, acc);
    }
    __syncthreads();
    int wa = tid >> 5, lane = tid & 31;
    for (int p = wa; p < cA * cA; p += 8) {
        int a = p / cA, b = p % cA;
        float acc = 0.f;
        for (int r = lane; r < cD; r += 32) acc += s_ae[a * cD + r] * s_ae[b * cD + r];
        for (int o = 16; o > 0; o >>= 1) acc += __shfl_xor_sync(0xffffffffu, acc, o);
        if (lane == 0) s_dot[p] = acc;
    }
    __syncthreads();
    if (tid < cA) {
        float mx = -1e30f;
        for (int b = 0; b < cA; ++b) mx = fmaxf(mx, s_dot[tid * cA + b]);
        float e[cA], sum = 0.f;
        for (int b = 0; b < cA; ++b) { e[b] = expf(s_dot[tid * cA + b] - mx); sum += e[b]; }
        float inv = 1.f / sum;
        for (int b = 0; b < cA; ++b) s_a2a[tid * cA + b] = e[b] * inv;
    }
    __syncthreads();
    for (int idx = tid; idx < cA * cD; idx += 256) {
        int a = idx / cD, d = idx % cD;
        float acc = 0.f;
#pragma unroll
        for (int b = 0; b < cA; ++b) acc += s_a2a[a * cA + b] * s_ae[b * cD + d];
        g_u2u[((long)(n * cA + a)) * cD + d] = acc;
        st_a4(1, n * cA + a, d, acc);
    }
}

// ---- SIMT GEMM (reg double-buffered), roles 0/1/2 ----
template <int ROLE>
__device__ void dev_gemm(char* smraw, int bx, int by, int bz,
                         const float* __restrict__ PA) {
    constexpr bool ATRANS = (ROLE == 0 || ROLE == 1);
    constexpr int BK = 16;
    float (*As)[68]  = reinterpret_cast<float(*)[68]>(smraw);
    float (*Bs)[128] = reinterpret_cast<float(*)[128]>(smraw + BK * 68 * 4);

    const float* A = nullptr; const float* B = nullptr;
    int ldA = 0, ldB = 0, n = bz, koE = cS;
    if (ROLE == 0) { A = PA + (long)n * cS * cE; ldA = cE;
                     B = g_sent + (long)n * cS * cD; ldB = cD; }
    if (ROLE == 1) { A = PA + (long)n * cS * cE; ldA = cE;
                     B = g_t2t + (long)n * cS * cS; ldB = cS; }
    if (ROLE == 2) { A = g_X + (long)n * cE * cS; ldA = cS;
                     B = g_sent + (long)n * cS * cD; ldB = cD; }
    int m0 = bx * 64, n0 = by * 128;
    int tid = threadIdx.x, tx = tid & 15, ty = tid >> 4;

    float2 acc[4][4];
#pragma unroll
    for (int i = 0; i < 4; ++i)
#pragma unroll
        for (int p = 0; p < 4; ++p) acc[i][p] = make_float2(0.f, 0.f);

    auto ldA_t = [&](int ko) -> float4 {
        if (ATRANS) {
            int r = tid >> 4, c4 = (tid & 15) << 2;
            return *(const float4*)(A + (long)(ko + r) * ldA + m0 + c4);
        } else {
            int m = tid >> 2, kq = (tid & 3) << 2;
            return *(const float4*)(A + (long)(m0 + m) * ldA + ko + kq);
        }
    };
    auto stA = [&](float4 v) {
        if (ATRANS) {
            int r = tid >> 4, c4 = (tid & 15) << 2;
            As[r][c4] = v.x; As[r][c4 + 1] = v.y; As[r][c4 + 2] = v.z; As[r][c4 + 3] = v.w;
        } else {
            int m = tid >> 2, kq = (tid & 3) << 2;
            As[kq][m] = v.x; As[kq + 1][m] = v.y; As[kq + 2][m] = v.z; As[kq + 3][m] = v.w;
        }
    };
    auto ldB_t = [&](int ko, float4& b0, float4& b1) {
        int r = tid >> 5, c4 = (tid & 31) << 2;
        b0 = *(const float4*)(B + (long)(ko + r) * ldB + n0 + c4);
        b1 = *(const float4*)(B + (long)(ko + r + 8) * ldB + n0 + c4);
    };
    auto stB = [&](float4 b0, float4 b1) {
        int r = tid >> 5, c4 = (tid & 31) << 2;
        *(float4*)&Bs[r][c4] = b0;
        *(float4*)&Bs[r + 8][c4] = b1;
    };

    { float4 a0 = ldA_t(0); float4 b0, b1; ldB_t(0, b0, b1);
      stA(a0); stB(b0, b1); }
    __syncthreads();
    for (int ko = 0; ko < koE; ko += BK) {
        bool has = (ko + BK) < koE;
        float4 nA, nB0, nB1;
        if (has) { nA = ldA_t(ko + BK); ldB_t(ko + BK, nB0, nB1); }
#pragma unroll
        for (int kk = 0; kk < BK; ++kk) {
            float4 av = *(const float4*)&As[kk][ty << 2];
            float a_[4] = {av.x, av.y, av.z, av.w};
            float2 b_[4];
#pragma unroll
            for (int p = 0; p < 4; ++p)
                b_[p] = *(const float2*)&Bs[kk][(tx << 1) + (p << 5)];
#pragma unroll
            for (int i = 0; i < 4; ++i) {
                float2 ad = make_float2(a_[i], a_[i]);
#pragma unroll
                for (int p = 0; p < 4; ++p) fma2(acc[i][p], ad, b_[p]);
            }
        }
        __syncthreads();
        if (has) { stA(nA); stB(nB0, nB1); __syncthreads(); }
    }
#pragma unroll
    for (int i = 0; i < 4; ++i) {
        int m = m0 + (ty << 2) + i;
#pragma unroll
        for (int p = 0; p < 4; ++p) {
            int col = n0 + (tx << 1) + (p << 5);
            float2 v = acc[i][p];
            if (ROLE == 0 || ROLE == 2) {
                int chunk = (ROLE == 0) ? 0 : 1;
                long off = (((long)((chunk * 16 + n) * 12 + (col >> 6))) * 128 + m) * 128 +
                           (((col & 63) * 2) ^ ((m & 7) << 4));
                *(uint32_t*)((char*)g_Atil + off) = pkbf(v.x, v.y);
                if (ROLE == 0)
                    *(float2*)&g_ent[((long)(n * cE + m)) * cD + col] = v;
            } else {
                *(float2*)&g_X[((long)(n * cE + m)) * cS + col] = v;
            }
        }
    }
}

// ---- w2: fat blocks (argemb in smem, 4 e-rows per warp) ----
__device__ void dev_w2(char* sm, int u) {
    int n = u >> 2, eq = u & 3;
    float* s_ag = (float*)sm;                // 9*768 floats
    int tid = threadIdx.x;
    for (int i = tid; i < cA * cD; i += 256)
        s_ag[i] = g_argemb[(long)n * cA * cD + i];
    __syncthreads();
    int wid = tid >> 5, lane = tid & 31;
#pragma unroll
    for (int rr = 0; rr < 4; ++rr) {
        int e = eq * 32 + wid * 4 + rr;
        const float* er = g_ent + ((long)(n * cE + e)) * cD;
        float acc[cA];
#pragma unroll
        for (int a = 0; a < cA; ++a) acc[a] = 0.f;
        for (int r = lane; r < cD; r += 32) {
            float ev = er[r];
#pragma unroll
            for (int a = 0; a < cA; ++a) acc[a] += ev * s_ag[a * cD + r];
        }
#pragma unroll
        for (int a = 0; a < cA; ++a) {
            float v = acc[a];
            for (int o = 16; o > 0; o >>= 1) v += __shfl_xor_sync(0xffffffffu, v, o);
            if (lane == 0)
                g_w[(n * cE + e) * cA + a] = (v * 0.03608439182435161f - 5.0f) * 0.5f;
        }
    }
}

// ---- atok2: per-(n, col-chunk), ent read ONCE; all 9 a's accumulated -------
__device__ void dev_atok2(char* sm, int u) {
    int n = u / 6, nt = u % 6;
    float* sw = (float*)sm;                  // 128*9 floats
    int tid = threadIdx.x;
    if (tid < cE)
#pragma unroll
        for (int a = 0; a < cA; ++a)
            sw[tid * cA + a] = g_w[(n * cE + tid) * cA + a];
    __syncthreads();
    int col = tid & 127, h = tid >> 7;       // h in {0,1}: a = h, h+2, ...
    float acc[5] = {0.f, 0.f, 0.f, 0.f, 0.f};
    const float* base = g_ent + (long)n * cE * cD + nt * 128 + col;
    for (int e = 0; e < cE; ++e) {
        float v = base[(long)e * cD];
        int idx = 0;
#pragma unroll
        for (int a = 0; a < cA; ++a)
            if ((a & 1) == h) acc[idx++] += sw[e * cA + a] * v;
    }
    {
        int idx = 0;
#pragma unroll
        for (int a = 0; a < cA; ++a)
            if ((a & 1) == h) st_a4(2, n * cA + a, nt * 128 + col, acc[idx++]);
    }
}

// ---- unified HMMA pipeline: all blocks 12 iters, 3-stage bulk-copy --------
constexpr int EP_TILE  = 16384;
constexpr int EP_STG   = 2 * EP_TILE;
constexpr int EP_NST   = 3;
constexpr int EP_SMEM  = 128 + EP_NST * EP_STG;   // 98432

__device__ void dev_hmma(char* sm, int bid) {
    uint32_t smB = smem_u32(sm);
    // 0..191: epart splitK (ch=bid/96); 192..227: gemm4; 228..239: atokW4
    const char* Ab; const char* Bb; float* dst;
    bool guard = false;
    if (bid < 192) {
        int ch = bid / 96, u = bid % 96;
        int mt = u & 15, nt = u >> 4;
        Ab = (const char*)g_Atil + ((long)((ch * 16 + mt) * 12)) * EP_TILE;
        Bb = (const char*)g_Btil + ((long)((ch * 6 + nt) * 12)) * EP_TILE;
        dst = (ch ? g_Epart2 : g_Epart) + (long)(mt * 128) * cNH + nt * 128;
    } else if (bid < 228) {
        int i = bid - 192, ch = i / 12, u = i % 12;
        int mt = u / 6, nt = u % 6;
        int ach = (ch == 1) ? 1 : 0;
        Ab = (const char*)g_Atil4 + ((long)((ach * 2 + mt) * 12)) * EP_TILE;
        Bb = (const char*)g_Btil + ((long)(((3 + ch) * 6 + nt) * 12)) * EP_TILE;
        dst = g_S4 + (long)ch * SZS + (long)(mt * 128) * cNH + nt * 128;
    } else {
        int i = bid - 228, mt = i / 6, nt = i % 6;
        Ab = (const char*)g_Atil4 + ((long)((4 + mt) * 12)) * EP_TILE;
        Bb = (const char*)g_Btil + ((long)((2 * 6 + nt) * 12)) * EP_TILE;
        dst = g_AtokW4 + (long)(mt * 128) * cNH + nt * 128;
        guard = (mt == 1);                  // rows 128..255 -> only 128..143 valid
    }
    int tid = threadIdx.x, lane = tid & 31, wid = tid >> 5;
    int warpM = (wid & 3) * 32, warpN = (wid >> 2) * 64;
    int lrow = lane & 7, lsel = lane >> 3;

    if (tid == 0)
        for (int s = 0; s < EP_NST; ++s)
            asm volatile("mbarrier.init.shared.b64 [%0], 1;" :: "r"(smB + s * 8) : "memory");
    __syncthreads();

    auto issue = [&](int t, int stg) {
        uint32_t mbar = smB + stg * 8;
        uint32_t dsts = smB + 128 + stg * EP_STG;
        asm volatile("mbarrier.arrive.expect_tx.shared.b64 _, [%0], %1;"
                     :: "r"(mbar), "r"((uint32_t)EP_STG) : "memory");
        asm volatile("cp.async.bulk.shared::cta.global.mbarrier::complete_tx::bytes "
                     "[%0], [%1], %2, [%3];"
                     :: "r"(dsts), "l"(Ab + (long)t * EP_TILE),
                        "r"((uint32_t)EP_TILE), "r"(mbar) : "memory");
        asm volatile("cp.async.bulk.shared::cta.global.mbarrier::complete_tx::bytes "
                     "[%0], [%1], %2, [%3];"
                     :: "r"(dsts + EP_TILE), "l"(Bb + (long)t * EP_TILE),
                        "r"((uint32_t)EP_TILE), "r"(mbar) : "memory");
    };
    if (tid == 0) { issue(0, 0); issue(1, 1); issue(2, 2); }

    float acc[2][8][4];
#pragma unroll
    for (int mi = 0; mi < 2; ++mi)
#pragma unroll
        for (int ni = 0; ni < 8; ++ni)
#pragma unroll
            for (int c = 0; c < 4; ++c) acc[mi][ni][c] = 0.f;

    uint32_t ph[EP_NST] = {0, 0, 0};
    for (int t = 0; t < 12; ++t) {
        int stg = t % EP_NST;
        mbar_wait(smB + stg * 8, ph[stg]);
        ph[stg] ^= 1;
        uint32_t aS = smB + 128 + stg * EP_STG, bS = aS + EP_TILE;
#pragma unroll
        for (int ks = 0; ks < 64; ks += 16) {
            uint32_t kbyte = (uint32_t)(ks * 2 + ((lsel >> 1) << 4));
            uint32_t afr[2][4], bfr[4][4];
#pragma unroll
            for (int mi = 0; mi < 2; ++mi) {
                int row = warpM + mi * 16 + lrow + ((lsel & 1) << 3);
                ldsm4(afr[mi], aS + row * 128 + (kbyte ^ ((row & 7) << 4)));
            }
#pragma unroll
            for (int g = 0; g < 4; ++g) {
                int row = warpN + g * 16 + lrow + ((lsel & 1) << 3);
                ldsm4(bfr[g], bS + row * 128 + (kbyte ^ ((row & 7) << 4)));
            }
#pragma unroll
            for (int g = 0; g < 4; ++g) {
                mma16816(acc[0][2 * g],     afr[0], bfr[g][0], bfr[g][2]);
                mma16816(acc[0][2 * g + 1], afr[0], bfr[g][1], bfr[g][3]);
                mma16816(acc[1][2 * g],     afr[1], bfr[g][0], bfr[g][2]);
                mma16816(acc[1][2 * g + 1], afr[1], bfr[g][1], bfr[g][3]);
            }
        }
        __syncthreads();
        if (t + EP_NST < 12 && tid == 0) issue(t + EP_NST, stg);
    }

#pragma unroll
    for (int mi = 0; mi < 2; ++mi)
#pragma unroll
        for (int ni = 0; ni < 8; ++ni) {
            int r = warpM + mi * 16 + (lane >> 2);
            int c = warpN + ni * 8 + (lane & 3) * 2;
            if (!guard || r < 16)
                *(float2*)&dst[(long)r * cNH + c] =
                    make_float2(acc[mi][ni][0], acc[mi][ni][1]);
            if (!guard || r + 8 < 16)
                *(float2*)&dst[(long)(r + 8) * cNH + c] =
                    make_float2(acc[mi][ni][2], acc[mi][ni][3]);
        }
}

// ---- final ----
__device__ void dev_final(char* sm, int bid,
                          const float* __restrict__ b1, const float* __restrict__ W2,
                          const float* __restrict__ b2, const int* __restrict__ argmap,
                          float* __restrict__ out) {
    float* sEp    = (float*)sm;
    float* sw9    = (float*)(sm + 3072);
    float* sScore = (float*)(sm + 3136);
    int n = bid >> 7, e = bid & 127;
    int tid = threadIdx.x;
    if (tid < cA) sw9[tid] = g_w[(n * cE + e) * cA + tid];
    __syncthreads();
    const float* Y2b = g_S4 + 2L * SZS;
    for (int r = tid; r < cNH; r += 256) {
        long ro = ((long)(n * cE + e)) * cNH + r;
        float s = g_Epart[ro] + g_Epart2[ro] + b1[r];
#pragma unroll
        for (int a = 0; a < cA; ++a) s += sw9[a] * Y2b[((long)(n * cA + a)) * cNH + r];
        sEp[r] = s;
    }
    __syncthreads();
    int wid = tid >> 5, lane = tid & 31;
    for (int a = wid; a < cA; a += 8) {
        long rowoff = ((long)(n * cA + a)) * cNH;
        const float* ap0 = g_S4 + rowoff;
        const float* ap1 = g_S4 + SZS + rowoff;
        const float* apL = g_AtokW4 + rowoff;
        float acc = 0.f;
        for (int r = lane; r < cNH; r += 32) {
            float pre = sEp[r] + ap0[r] + ap1[r] + apL[r];
            float hv = 0.5f * pre * (1.0f + erff(pre * 0.7071067811865476f));
            acc += hv * W2[r];
        }
        for (int o = 16; o > 0; o >>= 1) acc += __shfl_xor_sync(0xffffffffu, acc, o);
        if (lane == 0) sScore[a] = acc + b2[0];
    }
    __syncthreads();
    if (tid < cROLES) {
        float v = -1000000.0f;
#pragma unroll
        for (int a = 0; a < cA; ++a)
            if (argmap[n * cA + a] == tid) v = sScore[a];
        out[((long)(n * cE + e)) * cROLES + tid] = v;
    }
}

// ======================= phase kernels ======================================
__global__ void __launch_bounds__(256, 1) k_p1(const float* attn, const float* emb,
                                               const int* idxs, const float* W1) {
    extern __shared__ char sm[];
    int b = blockIdx.x;
    if (b < 2048) dev_t2t(sm, b, attn, idxs);
    else if (b < 4240) dev_gather(b - 2048, emb, idxs);
    else dev_convW(sm, b - 4240, W1);
}
__global__ void __launch_bounds__(256, 1) k_p2(const float* em, const float* argw) {
    extern __shared__ char sm[];
    int b = blockIdx.x;
    if (b < 192)      dev_gemm<0>(sm, b & 1, (b >> 1) % 6, b / 12, em);
    else if (b < 224) { int i = b - 192; dev_gemm<1>(sm, i & 1, 0, i >> 1, em); }
    else              dev_argsmall(sm, b - 224, argw);
}
// p3: gemm2(192) + w2(64)
__global__ void __launch_bounds__(256, 1) k_p3() {
    extern __shared__ char sm[];
    int b = blockIdx.x;
    if (b < 192) dev_gemm<2>(sm, b & 1, (b >> 1) % 6, b / 12, nullptr);
    else         dev_w2(sm, b - 192);
}
// p4a: atok2 (needs w from p3), 96 blocks
__global__ void __launch_bounds__(256, 1) k_p4a() {
    extern __shared__ char sm[];
    dev_atok2(sm, blockIdx.x);
}
// p4b: 240 uniform 12-iter HMMA blocks
__global__ void __launch_bounds__(256, 1) k_p4b() {
    extern __shared__ char sm[];
    dev_hmma(sm, blockIdx.x);
}
__global__ void __launch_bounds__(256, 1) k_p5(const float* b1, const float* W2,
                                               const float* b2, const int* argmap,
                                               float* out) {
    extern __shared__ char sm[];
    dev_final(sm, blockIdx.x, b1, W2, b2, argmap, out);
}

// ---------------- launch ----------------------------------------------------
extern "C" void kernel_launch(void* const* d_in, const int* in_sizes, int n_in,
                              void* d_out, int out_size) {
    const float* emb  = (const float*)d_in[0];
    const float* attn = (const float*)d_in[1];
    const float* em   = (const float*)d_in[2];
    const float* argw = (const float*)d_in[3];
    const float* W1   = (const float*)d_in[5];
    const float* b1   = (const float*)d_in[6];
    const float* W2   = (const float*)d_in[7];
    const float* b2   = (const float*)d_in[8];
    const int*   idxs = (const int*)d_in[9];
    const int*   amap = (const int*)d_in[10];
    float* out = (float*)d_out;

    cudaFuncSetAttribute(k_p4b, cudaFuncAttributeMaxDynamicSharedMemorySize, EP_SMEM);

    k_p1 <<<7696, 256, 38912>>>(attn, emb, idxs, W1);
    k_p2 <<<240,  256, 28656>>>(em, argw);
    k_p3 <<<256,  256, 27648>>>();
    k_p4a<<<96,   256, 4608>>>();
    k_p4b<<<240,  256, EP_SMEM>>>();
    k_p5 <<<2048, 256, 3200>>>(b1, W2, b2, amap, out);
}

// round 14
// speedup vs baseline: 1.0697x; 1.0697x over previous
#include <cuda_runtime.h>
#include <cuda_bf16.h>
#include <cstdint>

constexpr int cN  = 16, cL = 256, cS = 128, cE = 128, cA = 9;
constexpr int cD  = 768, cNH = 768, cIDXW = 130, cROLES = 24;
constexpr int cM  = cN * cA;            // 144
constexpr int SZS = 256 * cNH;          // padded slice rows

// ---------------- scratch ---------------------------------------------------
__device__ float g_sent   [cN * cS * cD];
__device__ float g_argraw [cN * cA * cD];
__device__ float g_argemb [cN * cA * cD];
__device__ float g_u2u    [cN * cA * cD];
__device__ float g_t2t    [cN * cS * cS];
__device__ float g_ent    [cN * cE * cD];
__device__ float g_X      [cN * cE * cS];
__device__ float g_w      [cN * cE * cA];
__device__ float g_Epart  [cN * cE * cNH];
__device__ float g_Epart2 [cN * cE * cNH];
__device__ float g_S4     [3 * SZS];       // argemb@W1, u2u@W5, argemb@W2 (padded)
__device__ float g_AtokW4 [cM * cNH];
__device__ __nv_bfloat16 g_Atil [2 * cN * cE * cD];  // tiled bf16 {ent, Ah2h}
__device__ __nv_bfloat16 g_Atil4[3 * 256 * cD];      // tiled bf16 {argemb, u2u, atok}
__device__ __nv_bfloat16 g_Btil [6 * cNH * cD];      // tiled bf16 W {0,3,4,1,5,2}

// ---------------- helpers ---------------------------------------------------
__device__ __forceinline__ void fma2(float2& d, float2 a, float2 b) {
    asm("fma.rn.f32x2 %0, %1, %2, %0;"
        : "+l"(reinterpret_cast<unsigned long long&>(d))
        : "l"(reinterpret_cast<unsigned long long&>(a)),
          "l"(reinterpret_cast<unsigned long long&>(b)));
}
__device__ __forceinline__ uint32_t smem_u32(const void* p) {
    return (uint32_t)__cvta_generic_to_shared(p);
}
__device__ __forceinline__ uint32_t pkbf(float a, float b) {
    __nv_bfloat162 h = __floats2bfloat162_rn(a, b);
    return *reinterpret_cast<uint32_t*>(&h);
}
__device__ __forceinline__ void ldsm4(uint32_t* r, uint32_t addr) {
    asm volatile("ldmatrix.sync.aligned.m8n8.x4.shared.b16 {%0,%1,%2,%3}, [%4];"
        : "=r"(r[0]), "=r"(r[1]), "=r"(r[2]), "=r"(r[3]) : "r"(addr));
}
__device__ __forceinline__ void mma16816(float* c, const uint32_t* a,
                                         uint32_t b0, uint32_t b1) {
    asm volatile(
        "mma.sync.aligned.m16n8k16.row.col.f32.bf16.bf16.f32 "
        "{%0,%1,%2,%3}, {%4,%5,%6,%7}, {%8,%9}, {%0,%1,%2,%3};"
        : "+f"(c[0]), "+f"(c[1]), "+f"(c[2]), "+f"(c[3])
        : "r"(a[0]), "r"(a[1]), "r"(a[2]), "r"(a[3]), "r"(b0), "r"(b1));
}
__device__ __forceinline__ void mbar_wait(uint32_t mbar, uint32_t parity) {
    uint32_t done;
    asm volatile("{\n\t.reg .pred p;\n\t"
        "mbarrier.try_wait.parity.acquire.cta.shared::cta.b64 p, [%1], %2;\n\t"
        "selp.b32 %0, 1, 0, p;\n\t}" : "=r"(done) : "r"(mbar), "r"(parity) : "memory");
    while (!done)
        asm volatile("{\n\t.reg .pred p;\n\t"
            "mbarrier.try_wait.parity.acquire.cta.shared::cta.b64 p, [%1], %2, 0x989680;\n\t"
            "selp.b32 %0, 1, 0, p;\n\t}" : "=r"(done) : "r"(mbar), "r"(parity) : "memory");
}

// ======================= role device functions ==============================

// ---- gather ----
__device__ void dev_gather(int row, const float* __restrict__ emb,
                           const int* __restrict__ idxs) {
    int tid = threadIdx.x;
    if (tid >= 192) return;
    if (row < cN * cS) {
        int n = row >> 7, s = row & 127;
        int src = idxs[n * cIDXW + s];
        ((float4*)(g_sent + (long)row * cD))[tid] =
            ((const float4*)(emb + ((long)n * cL + src) * cD))[tid];
    } else {
        int r = row - cN * cS, n = r / cA, a = r % cA;
        int src = idxs[n * cIDXW + cS] + 1 + a;
        ((float4*)(g_argraw + (long)r * cD))[tid] =
            ((const float4*)(emb + ((long)n * cL + src) * cD))[tid];
    }
}

// ---- t2t ----
__device__ void dev_t2t(char* sm, int bid, const float* __restrict__ attn,
                        const int* __restrict__ idxs) {
    float* rows = (float*)sm;                    // 36*256
    int*   sc   = (int*)(sm + 36864);
    float* r0   = (float*)(sm + 37376);
    float* r1   = (float*)(sm + 37888);
    float* r2   = (float*)(sm + 38400);
    int n = bid >> 7, a = bid & 127;
    int tid = threadIdx.x;
    if (tid < cS) sc[tid] = idxs[n * cIDXW + tid];
    __syncthreads();
    int i = sc[a];
    for (int idx = tid; idx < 36 * 64; idx += 256) {
        int r = idx >> 6, c = idx & 63;
        int l = r / 12, h = r - l * 12;
        long off = ((((long)l * cN + n) * 12 + h) * cL + i) * cL;
        *(float4*)&rows[r * 256 + c * 4] = *(const float4*)(attn + off + c * 4);
    }
    __syncthreads();
    float a0 = 0.f, a1 = 0.f, a2 = 0.f;
    if (tid < cS) {
        int j = sc[tid];
#pragma unroll
        for (int h = 0; h < 12; ++h) {
            a0 += rows[h * 256 + j];
            a1 += rows[(12 + h) * 256 + j];
            a2 += rows[(24 + h) * 256 + j];
        }
        r0[tid] = a0; r1[tid] = a1; r2[tid] = a2;
    }
    __syncthreads();
    for (int st = 64; st > 0; st >>= 1) {
        if (tid < st) { r0[tid] += r0[tid + st]; r1[tid] += r1[tid + st]; r2[tid] += r2[tid + st]; }
        __syncthreads();
    }
    if (tid < cS) {
        float d0 = r0[0] * (1.f / 12.f) + 1e-9f;
        float d1 = r1[0] * (1.f / 12.f) + 1e-9f;
        float d2 = r2[0] * (1.f / 12.f) + 1e-9f;
        g_t2t[((long)(n * cS + a)) * cS + tid] =
            ((a0 * (1.f / 12.f)) / d0 + (a1 * (1.f / 12.f)) / d1 +
             (a2 * (1.f / 12.f)) / d2) * (1.f / 3.f);
    }
}

// ---- convW: W1 blocks {0,3,4,1,5,2} -> tiled swizzled bf16 ----
__device__ void dev_convW(char* sm, int bid, const float* __restrict__ W1) {
    float (*tile)[33] = (float(*)[33])sm;
    int bx = bid % 24, by = (bid / 24) % 24, blk = bid / 576;  // 0..5
    const int map[6] = {0, 3, 4, 1, 5, 2};
    int wb = map[blk];
    int tid = threadIdx.x, tx = tid & 31, ty = tid >> 5;
    const float* src = W1 + (long)wb * cD * cNH;
    int k0 = by * 32, n0 = bx * 32;
#pragma unroll
    for (int j = 0; j < 4; ++j)
        tile[ty + j * 8][tx] = src[(long)(k0 + ty + j * 8) * cNH + n0 + tx];
    __syncthreads();
#pragma unroll
    for (int j = 0; j < 4; ++j) {
        int nIdx = n0 + ty + j * 8, kIdx = k0 + tx;
        long off = (((long)(blk * 6 + (nIdx >> 7)) * 12 + (kIdx >> 6)) * 128 +
                    (nIdx & 127)) * 128 +
                   (((kIdx & 63) * 2) ^ ((nIdx & 7) << 4));
        *(__nv_bfloat16*)((char*)g_Btil + off) = __float2bfloat16_rn(tile[tx][ty + j * 8]);
    }
}

// ---- argsmall (+ bf16 tiled argemb/u2u) ----
__device__ __forceinline__ void st_a4(int chunk, int m, int d, float v) {
    int mt = m >> 7, r = m & 127;
    long off = (((long)(chunk * 2 + mt) * 12 + (d >> 6)) * 128 + r) * 128 +
               (((d & 63) * 2) ^ ((r & 7) << 4));
    *(__nv_bfloat16*)((char*)g_Atil4 + off) = __float2bfloat16_rn(v);
}
__device__ void dev_argsmall(char* sm, int n, const float* __restrict__ argw) {
    float* s_ae  = (float*)sm;
    float* s_aw  = (float*)(sm + 27648);
    float* s_dot = (float*)(sm + 27984);
    float* s_a2a = (float*)(sm + 28320);
    int tid = threadIdx.x;
    if (tid < cA * cA) s_aw[tid] = argw[n * cA * cA + tid];
    __syncthreads();
    for (int idx = tid; idx < cA * cD; idx += 256) {
        int a = idx / cD, d = idx % cD;
        float acc = 0.f;
#pragma unroll
        for (int k = 0; k < cA; ++k)
            acc += g_argraw[((long)(n * cA + k)) * cD + d] * s_aw[k * cA + a];
        s_ae[a * cD + d] = acc;
        g_argemb[((long)(n * cA + a)) * cD + d] = acc;
        st_a4(0, n * cA + a, d, acc);
    }
    __syncthreads();
    int wa = tid >> 5, lane = tid & 31;
    for (int p = wa; p < cA * cA; p += 8) {
        int a = p / cA, b = p % cA;
        float acc = 0.f;
        for (int r = lane; r < cD; r += 32) acc += s_ae[a * cD + r] * s_ae[b * cD + r];
        for (int o = 16; o > 0; o >>= 1) acc += __shfl_xor_sync(0xffffffffu, acc, o);
        if (lane == 0) s_dot[p] = acc;
    }
    __syncthreads();
    if (tid < cA) {
        float mx = -1e30f;
        for (int b = 0; b < cA; ++b) mx = fmaxf(mx, s_dot[tid * cA + b]);
        float e[cA], sum = 0.f;
        for (int b = 0; b < cA; ++b) { e[b] = expf(s_dot[tid * cA + b] - mx); sum += e[b]; }
        float inv = 1.f / sum;
        for (int b = 0; b < cA; ++b) s_a2a[tid * cA + b] = e[b] * inv;
    }
    __syncthreads();
    for (int idx = tid; idx < cA * cD; idx += 256) {
        int a = idx / cD, d = idx % cD;
        float acc = 0.f;
#pragma unroll
        for (int b = 0; b < cA; ++b) acc += s_a2a[a * cA + b] * s_ae[b * cD + d];
        g_u2u[((long)(n * cA + a)) * cD + d] = acc;
        st_a4(1, n * cA + a, d, acc);
    }
}

// ---- SIMT GEMM (reg double-buffered), roles 0/1/2 ----
template <int ROLE>
__device__ void dev_gemm(char* smraw, int bx, int by, int bz,
                         const float* __restrict__ PA) {
    constexpr bool ATRANS = (ROLE == 0 || ROLE == 1);
    constexpr int BK = 16;
    float (*As)[68]  = reinterpret_cast<float(*)[68]>(smraw);
    float (*Bs)[128] = reinterpret_cast<float(*)[128]>(smraw + BK * 68 * 4);

    const float* A = nullptr; const float* B = nullptr;
    int ldA = 0, ldB = 0, n = bz, koE = cS;
    if (ROLE == 0) { A = PA + (long)n * cS * cE; ldA = cE;
                     B = g_sent + (long)n * cS * cD; ldB = cD; }
    if (ROLE == 1) { A = PA + (long)n * cS * cE; ldA = cE;
                     B = g_t2t + (long)n * cS * cS; ldB = cS; }
    if (ROLE == 2) { A = g_X + (long)n * cE * cS; ldA = cS;
                     B = g_sent + (long)n * cS * cD; ldB = cD; }
    int m0 = bx * 64, n0 = by * 128;
    int tid = threadIdx.x, tx = tid & 15, ty = tid >> 4;

    float2 acc[4][4];
#pragma unroll
    for (int i = 0; i < 4; ++i)
#pragma unroll
        for (int p = 0; p < 4; ++p) acc[i][p] = make_float2(0.f, 0.f);

    auto ldA_t = [&](int ko) -> float4 {
        if (ATRANS) {
            int r = tid >> 4, c4 = (tid & 15) << 2;
            return *(const float4*)(A + (long)(ko + r) * ldA + m0 + c4);
        } else {
            int m = tid >> 2, kq = (tid & 3) << 2;
            return *(const float4*)(A + (long)(m0 + m) * ldA + ko + kq);
        }
    };
    auto stA = [&](float4 v) {
        if (ATRANS) {
            int r = tid >> 4, c4 = (tid & 15) << 2;
            As[r][c4] = v.x; As[r][c4 + 1] = v.y; As[r][c4 + 2] = v.z; As[r][c4 + 3] = v.w;
        } else {
            int m = tid >> 2, kq = (tid & 3) << 2;
            As[kq][m] = v.x; As[kq + 1][m] = v.y; As[kq + 2][m] = v.z; As[kq + 3][m] = v.w;
        }
    };
    auto ldB_t = [&](int ko, float4& b0, float4& b1) {
        int r = tid >> 5, c4 = (tid & 31) << 2;
        b0 = *(const float4*)(B + (long)(ko + r) * ldB + n0 + c4);
        b1 = *(const float4*)(B + (long)(ko + r + 8) * ldB + n0 + c4);
    };
    auto stB = [&](float4 b0, float4 b1) {
        int r = tid >> 5, c4 = (tid & 31) << 2;
        *(float4*)&Bs[r][c4] = b0;
        *(float4*)&Bs[r + 8][c4] = b1;
    };

    { float4 a0 = ldA_t(0); float4 b0, b1; ldB_t(0, b0, b1);
      stA(a0); stB(b0, b1); }
    __syncthreads();
    for (int ko = 0; ko < koE; ko += BK) {
        bool has = (ko + BK) < koE;
        float4 nA, nB0, nB1;
        if (has) { nA = ldA_t(ko + BK); ldB_t(ko + BK, nB0, nB1); }
#pragma unroll
        for (int kk = 0; kk < BK; ++kk) {
            float4 av = *(const float4*)&As[kk][ty << 2];
            float a_[4] = {av.x, av.y, av.z, av.w};
            float2 b_[4];
#pragma unroll
            for (int p = 0; p < 4; ++p)
                b_[p] = *(const float2*)&Bs[kk][(tx << 1) + (p << 5)];
#pragma unroll
            for (int i = 0; i < 4; ++i) {
                float2 ad = make_float2(a_[i], a_[i]);
#pragma unroll
                for (int p = 0; p < 4; ++p) fma2(acc[i][p], ad, b_[p]);
            }
        }
        __syncthreads();
        if (has) { stA(nA); stB(nB0, nB1); __syncthreads(); }
    }
#pragma unroll
    for (int i = 0; i < 4; ++i) {
        int m = m0 + (ty << 2) + i;
#pragma unroll
        for (int p = 0; p < 4; ++p) {
            int col = n0 + (tx << 1) + (p << 5);
            float2 v = acc[i][p];
            if (ROLE == 0 || ROLE == 2) {
                int chunk = (ROLE == 0) ? 0 : 1;
                long off = (((long)((chunk * 16 + n) * 12 + (col >> 6))) * 128 + m) * 128 +
                           (((col & 63) * 2) ^ ((m & 7) << 4));
                *(uint32_t*)((char*)g_Atil + off) = pkbf(v.x, v.y);
                if (ROLE == 0)
                    *(float2*)&g_ent[((long)(n * cE + m)) * cD + col] = v;
            } else {
                *(float2*)&g_X[((long)(n * cE + m)) * cS + col] = v;
            }
        }
    }
}

// ---- w2: fat blocks (argemb in smem, 4 e-rows per warp) ----
__device__ void dev_w2(char* sm, int u) {
    int n = u >> 2, eq = u & 3;
    float* s_ag = (float*)sm;                // 9*768 floats
    int tid = threadIdx.x;
    for (int i = tid; i < cA * cD; i += 256)
        s_ag[i] = g_argemb[(long)n * cA * cD + i];
    __syncthreads();
    int wid = tid >> 5, lane = tid & 31;
#pragma unroll
    for (int rr = 0; rr < 4; ++rr) {
        int e = eq * 32 + wid * 4 + rr;
        const float* er = g_ent + ((long)(n * cE + e)) * cD;
        float acc[cA];
#pragma unroll
        for (int a = 0; a < cA; ++a) acc[a] = 0.f;
        for (int r = lane; r < cD; r += 32) {
            float ev = er[r];
#pragma unroll
            for (int a = 0; a < cA; ++a) acc[a] += ev * s_ag[a * cD + r];
        }
#pragma unroll
        for (int a = 0; a < cA; ++a) {
            float v = acc[a];
            for (int o = 16; o > 0; o >>= 1) v += __shfl_xor_sync(0xffffffffu, v, o);
            if (lane == 0)
                g_w[(n * cE + e) * cA + a] = (v * 0.03608439182435161f - 5.0f) * 0.5f;
        }
    }
}

// ---- atok2: per-(n, col-chunk); e-loop batched by 8 for MLP ---------------
__device__ void dev_atok2(char* sm, int u) {
    int n = u / 6, nt = u % 6;
    float* sw = (float*)sm;                  // 128*9 floats
    int tid = threadIdx.x;
    if (tid < cE)
#pragma unroll
        for (int a = 0; a < cA; ++a)
            sw[tid * cA + a] = g_w[(n * cE + tid) * cA + a];
    __syncthreads();
    int col = tid & 127, h = tid >> 7;       // h in {0,1}: a = h, h+2, ...
    float acc[5] = {0.f, 0.f, 0.f, 0.f, 0.f};
    const float* base = g_ent + (long)n * cE * cD + nt * 128 + col;
    for (int e0 = 0; e0 < cE; e0 += 8) {
        float v[8];
#pragma unroll
        for (int j = 0; j < 8; ++j)          // 8 independent LDGs (MLP=8)
            v[j] = base[(long)(e0 + j) * cD];
#pragma unroll
        for (int j = 0; j < 8; ++j) {
            int idx = 0;
#pragma unroll
            for (int a = 0; a < cA; ++a)
                if ((a & 1) == h) acc[idx++] += sw[(e0 + j) * cA + a] * v[j];
        }
    }
    {
        int idx = 0;
#pragma unroll
        for (int a = 0; a < cA; ++a)
            if ((a & 1) == h) st_a4(2, n * cA + a, nt * 128 + col, acc[idx++]);
    }
}

// ---- unified HMMA pipeline: all blocks 12 iters, 3-stage bulk-copy --------
constexpr int EP_TILE  = 16384;
constexpr int EP_STG   = 2 * EP_TILE;
constexpr int EP_NST   = 3;
constexpr int EP_SMEM  = 128 + EP_NST * EP_STG;   // 98432

__device__ void dev_hmma(char* sm, int bid) {
    uint32_t smB = smem_u32(sm);
    // 0..191: epart splitK (ch=bid/96); 192..227: gemm4; 228..239: atokW4
    const char* Ab; const char* Bb; float* dst;
    bool guard = false;
    if (bid < 192) {
        int ch = bid / 96, u = bid % 96;
        int mt = u & 15, nt = u >> 4;
        Ab = (const char*)g_Atil + ((long)((ch * 16 + mt) * 12)) * EP_TILE;
        Bb = (const char*)g_Btil + ((long)((ch * 6 + nt) * 12)) * EP_TILE;
        dst = (ch ? g_Epart2 : g_Epart) + (long)(mt * 128) * cNH + nt * 128;
    } else if (bid < 228) {
        int i = bid - 192, ch = i / 12, u = i % 12;
        int mt = u / 6, nt = u % 6;
        int ach = (ch == 1) ? 1 : 0;
        Ab = (const char*)g_Atil4 + ((long)((ach * 2 + mt) * 12)) * EP_TILE;
        Bb = (const char*)g_Btil + ((long)(((3 + ch) * 6 + nt) * 12)) * EP_TILE;
        dst = g_S4 + (long)ch * SZS + (long)(mt * 128) * cNH + nt * 128;
    } else {
        int i = bid - 228, mt = i / 6, nt = i % 6;
        Ab = (const char*)g_Atil4 + ((long)((4 + mt) * 12)) * EP_TILE;
        Bb = (const char*)g_Btil + ((long)((2 * 6 + nt) * 12)) * EP_TILE;
        dst = g_AtokW4 + (long)(mt * 128) * cNH + nt * 128;
        guard = (mt == 1);                  // rows 128..255 -> only 128..143 valid
    }
    int tid = threadIdx.x, lane = tid & 31, wid = tid >> 5;
    int warpM = (wid & 3) * 32, warpN = (wid >> 2) * 64;
    int lrow = lane & 7, lsel = lane >> 3;

    if (tid == 0)
        for (int s = 0; s < EP_NST; ++s)
            asm volatile("mbarrier.init.shared.b64 [%0], 1;" :: "r"(smB + s * 8) : "memory");
    __syncthreads();

    auto issue = [&](int t, int stg) {
        uint32_t mbar = smB + stg * 8;
        uint32_t dsts = smB + 128 + stg * EP_STG;
        asm volatile("mbarrier.arrive.expect_tx.shared.b64 _, [%0], %1;"
                     :: "r"(mbar), "r"((uint32_t)EP_STG) : "memory");
        asm volatile("cp.async.bulk.shared::cta.global.mbarrier::complete_tx::bytes "
                     "[%0], [%1], %2, [%3];"
                     :: "r"(dsts), "l"(Ab + (long)t * EP_TILE),
                        "r"((uint32_t)EP_TILE), "r"(mbar) : "memory");
        asm volatile("cp.async.bulk.shared::cta.global.mbarrier::complete_tx::bytes "
                     "[%0], [%1], %2, [%3];"
                     :: "r"(dsts + EP_TILE), "l"(Bb + (long)t * EP_TILE),
                        "r"((uint32_t)EP_TILE), "r"(mbar) : "memory");
    };
    if (tid == 0) { issue(0, 0); issue(1, 1); issue(2, 2); }

    float acc[2][8][4];
#pragma unroll
    for (int mi = 0; mi < 2; ++mi)
#pragma unroll
        for (int ni = 0; ni < 8; ++ni)
#pragma unroll
            for (int c = 0; c < 4; ++c) acc[mi][ni][c] = 0.f;

    uint32_t ph[EP_NST] = {0, 0, 0};
    for (int t = 0; t < 12; ++t) {
        int stg = t % EP_NST;
        mbar_wait(smB + stg * 8, ph[stg]);
        ph[stg] ^= 1;
        uint32_t aS = smB + 128 + stg * EP_STG, bS = aS + EP_TILE;
#pragma unroll
        for (int ks = 0; ks < 64; ks += 16) {
            uint32_t kbyte = (uint32_t)(ks * 2 + ((lsel >> 1) << 4));
            uint32_t afr[2][4], bfr[4][4];
#pragma unroll
            for (int mi = 0; mi < 2; ++mi) {
                int row = warpM + mi * 16 + lrow + ((lsel & 1) << 3);
                ldsm4(afr[mi], aS + row * 128 + (kbyte ^ ((row & 7) << 4)));
            }
#pragma unroll
            for (int g = 0; g < 4; ++g) {
                int row = warpN + g * 16 + lrow + ((lsel & 1) << 3);
                ldsm4(bfr[g], bS + row * 128 + (kbyte ^ ((row & 7) << 4)));
            }
#pragma unroll
            for (int g = 0; g < 4; ++g) {
                mma16816(acc[0][2 * g],     afr[0], bfr[g][0], bfr[g][2]);
                mma16816(acc[0][2 * g + 1], afr[0], bfr[g][1], bfr[g][3]);
                mma16816(acc[1][2 * g],     afr[1], bfr[g][0], bfr[g][2]);
                mma16816(acc[1][2 * g + 1], afr[1], bfr[g][1], bfr[g][3]);
            }
        }
        __syncthreads();
        if (t + EP_NST < 12 && tid == 0) issue(t + EP_NST, stg);
    }

#pragma unroll
    for (int mi = 0; mi < 2; ++mi)
#pragma unroll
        for (int ni = 0; ni < 8; ++ni) {
            int r = warpM + mi * 16 + (lane >> 2);
            int c = warpN + ni * 8 + (lane & 3) * 2;
            if (!guard || r < 16)
                *(float2*)&dst[(long)r * cNH + c] =
                    make_float2(acc[mi][ni][0], acc[mi][ni][1]);
            if (!guard || r + 8 < 16)
                *(float2*)&dst[(long)(r + 8) * cNH + c] =
                    make_float2(acc[mi][ni][2], acc[mi][ni][3]);
        }
}

// ---- final ----
__device__ void dev_final(char* sm, int bid,
                          const float* __restrict__ b1, const float* __restrict__ W2,
                          const float* __restrict__ b2, const int* __restrict__ argmap,
                          float* __restrict__ out) {
    float* sEp    = (float*)sm;
    float* sw9    = (float*)(sm + 3072);
    float* sScore = (float*)(sm + 3136);
    int n = bid >> 7, e = bid & 127;
    int tid = threadIdx.x;
    if (tid < cA) sw9[tid] = g_w[(n * cE + e) * cA + tid];
    __syncthreads();
    const float* Y2b = g_S4 + 2L * SZS;
    for (int r = tid; r < cNH; r += 256) {
        long ro = ((long)(n * cE + e)) * cNH + r;
        float s = g_Epart[ro] + g_Epart2[ro] + b1[r];
#pragma unroll
        for (int a = 0; a < cA; ++a) s += sw9[a] * Y2b[((long)(n * cA + a)) * cNH + r];
        sEp[r] = s;
    }
    __syncthreads();
    int wid = tid >> 5, lane = tid & 31;
    for (int a = wid; a < cA; a += 8) {
        long rowoff = ((long)(n * cA + a)) * cNH;
        const float* ap0 = g_S4 + rowoff;
        const float* ap1 = g_S4 + SZS + rowoff;
        const float* apL = g_AtokW4 + rowoff;
        float acc = 0.f;
        for (int r = lane; r < cNH; r += 32) {
            float pre = sEp[r] + ap0[r] + ap1[r] + apL[r];
            float hv = 0.5f * pre * (1.0f + erff(pre * 0.7071067811865476f));
            acc += hv * W2[r];
        }
        for (int o = 16; o > 0; o >>= 1) acc += __shfl_xor_sync(0xffffffffu, acc, o);
        if (lane == 0) sScore[a] = acc + b2[0];
    }
    __syncthreads();
    if (tid < cROLES) {
        float v = -1000000.0f;
#pragma unroll
        for (int a = 0; a < cA; ++a)
            if (argmap[n * cA + a] == tid) v = sScore[a];
        out[((long)(n * cE + e)) * cROLES + tid] = v;
    }
}

// ======================= phase kernels ======================================
__global__ void __launch_bounds__(256, 1) k_p1(const float* attn, const float* emb,
                                               const int* idxs, const float* W1) {
    extern __shared__ char sm[];
    int b = blockIdx.x;
    if (b < 2048) dev_t2t(sm, b, attn, idxs);
    else if (b < 4240) dev_gather(b - 2048, emb, idxs);
    else dev_convW(sm, b - 4240, W1);
}
__global__ void __launch_bounds__(256, 1) k_p2(const float* em, const float* argw) {
    extern __shared__ char sm[];
    int b = blockIdx.x;
    if (b < 192)      dev_gemm<0>(sm, b & 1, (b >> 1) % 6, b / 12, em);
    else if (b < 224) { int i = b - 192; dev_gemm<1>(sm, i & 1, 0, i >> 1, em); }
    else              dev_argsmall(sm, b - 224, argw);
}
// p3: gemm2(192) + w2(64)
__global__ void __launch_bounds__(256, 1) k_p3() {
    extern __shared__ char sm[];
    int b = blockIdx.x;
    if (b < 192) dev_gemm<2>(sm, b & 1, (b >> 1) % 6, b / 12, nullptr);
    else         dev_w2(sm, b - 192);
}
// p4a: atok2 (needs w from p3), 96 blocks
__global__ void __launch_bounds__(256, 1) k_p4a() {
    extern __shared__ char sm[];
    dev_atok2(sm, blockIdx.x);
}
// p4b: 240 uniform 12-iter HMMA blocks
__global__ void __launch_bounds__(256, 1) k_p4b() {
    extern __shared__ char sm[];
    dev_hmma(sm, blockIdx.x);
}
__global__ void __launch_bounds__(256, 1) k_p5(const float* b1, const float* W2,
                                               const float* b2, const int* argmap,
                                               float* out) {
    extern __shared__ char sm[];
    dev_final(sm, blockIdx.x, b1, W2, b2, argmap, out);
}

// ---------------- launch ----------------------------------------------------
extern "C" void kernel_launch(void* const* d_in, const int* in_sizes, int n_in,
                              void* d_out, int out_size) {
    const float* emb  = (const float*)d_in[0];
    const float* attn = (const float*)d_in[1];
    const float* em   = (const float*)d_in[2];
    const float* argw = (const float*)d_in[3];
    const float* W1   = (const float*)d_in[5];
    const float* b1   = (const float*)d_in[6];
    const float* W2   = (const float*)d_in[7];
    const float* b2   = (const float*)d_in[8];
    const int*   idxs = (const int*)d_in[9];
    const int*   amap = (const int*)d_in[10];
    float* out = (float*)d_out;

    cudaFuncSetAttribute(k_p4b, cudaFuncAttributeMaxDynamicSharedMemorySize, EP_SMEM);

    k_p1 <<<7696, 256, 38912>>>(attn, emb, idxs, W1);
    k_p2 <<<240,  256, 28656>>>(em, argw);
    k_p3 <<<256,  256, 27648>>>();
    k_p4a<<<96,   256, 4608>>>();
    k_p4b<<<240,  256, EP_SMEM>>>();
    k_p5 <<<2048, 256, 3200>>>(b1, W2, b2, amap, out);
}

// round 15
// speedup vs baseline: 1.3784x; 1.2886x over previous
#include <cuda_runtime.h>
#include <cuda_bf16.h>
#include <cstdint>

constexpr int cN  = 16, cL = 256, cS = 128, cE = 128, cA = 9;
constexpr int cD  = 768, cNH = 768, cIDXW = 130, cROLES = 24;
constexpr int cM  = cN * cA;            // 144
constexpr int SZS = 256 * cNH;          // padded slice rows

// ---------------- scratch ---------------------------------------------------
__device__ float g_sent   [cN * cS * cD];
__device__ float g_argraw [cN * cA * cD];
__device__ float g_argemb [cN * cA * cD];
__device__ float g_u2u    [cN * cA * cD];
__device__ float g_t2t    [cN * cS * cS];
__device__ float g_ent    [cN * cE * cD];
__device__ float g_X      [cN * cE * cS];
__device__ float g_w      [cN * cE * cA];
__device__ float g_Epart  [cN * cE * cNH];
__device__ float g_Epart2 [cN * cE * cNH];
__device__ float g_S4     [3 * SZS];       // argemb@W1, u2u@W5, argemb@W2 (padded)
__device__ float g_AtokW4 [cM * cNH];
__device__ __nv_bfloat16 g_Atil [2 * cN * cE * cD];  // tiled bf16 {ent, Ah2h}
__device__ __nv_bfloat16 g_Atil4[3 * 256 * cD];      // tiled bf16 {argemb, u2u, atok}
__device__ __nv_bfloat16 g_Btil [6 * cNH * cD];      // tiled bf16 W {0,3,4,1,5,2}

// ---------------- helpers ---------------------------------------------------
__device__ __forceinline__ void fma2(float2& d, float2 a, float2 b) {
    asm("fma.rn.f32x2 %0, %1, %2, %0;"
        : "+l"(reinterpret_cast<unsigned long long&>(d))
        : "l"(reinterpret_cast<unsigned long long&>(a)),
          "l"(reinterpret_cast<unsigned long long&>(b)));
}
__device__ __forceinline__ uint32_t smem_u32(const void* p) {
    return (uint32_t)__cvta_generic_to_shared(p);
}
__device__ __forceinline__ uint32_t pkbf(float a, float b) {
    __nv_bfloat162 h = __floats2bfloat162_rn(a, b);
    return *reinterpret_cast<uint32_t*>(&h);
}
__device__ __forceinline__ void ldsm4(uint32_t* r, uint32_t addr) {
    asm volatile("ldmatrix.sync.aligned.m8n8.x4.shared.b16 {%0,%1,%2,%3}, [%4];"
        : "=r"(r[0]), "=r"(r[1]), "=r"(r[2]), "=r"(r[3]) : "r"(addr));
}
__device__ __forceinline__ void mma16816(float* c, const uint32_t* a,
                                         uint32_t b0, uint32_t b1) {
    asm volatile(
        "mma.sync.aligned.m16n8k16.row.col.f32.bf16.bf16.f32 "
        "{%0,%1,%2,%3}, {%4,%5,%6,%7}, {%8,%9}, {%0,%1,%2,%3};"
        : "+f"(c[0]), "+f"(c[1]), "+f"(c[2]), "+f"(c[3])
        : "r"(a[0]), "r"(a[1]), "r"(a[2]), "r"(a[3]), "r"(b0), "r"(b1));
}
__device__ __forceinline__ void mbar_wait(uint32_t mbar, uint32_t parity) {
    uint32_t done;
    asm volatile("{\n\t.reg .pred p;\n\t"
        "mbarrier.try_wait.parity.acquire.cta.shared::cta.b64 p, [%1], %2;\n\t"
        "selp.b32 %0, 1, 0, p;\n\t}" : "=r"(done) : "r"(mbar), "r"(parity) : "memory");
    while (!done)
        asm volatile("{\n\t.reg .pred p;\n\t"
            "mbarrier.try_wait.parity.acquire.cta.shared::cta.b64 p, [%1], %2, 0x989680;\n\t"
            "selp.b32 %0, 1, 0, p;\n\t}" : "=r"(done) : "r"(mbar), "r"(parity) : "memory");
}

// ======================= role device functions ==============================

// ---- gather ----
__device__ void dev_gather(int row, const float* __restrict__ emb,
                           const int* __restrict__ idxs) {
    int tid = threadIdx.x;
    if (tid >= 192) return;
    if (row < cN * cS) {
        int n = row >> 7, s = row & 127;
        int src = idxs[n * cIDXW + s];
        ((float4*)(g_sent + (long)row * cD))[tid] =
            ((const float4*)(emb + ((long)n * cL + src) * cD))[tid];
    } else {
        int r = row - cN * cS, n = r / cA, a = r % cA;
        int src = idxs[n * cIDXW + cS] + 1 + a;
        ((float4*)(g_argraw + (long)r * cD))[tid] =
            ((const float4*)(emb + ((long)n * cL + src) * cD))[tid];
    }
}

// ---- t2t ----
__device__ void dev_t2t(char* sm, int bid, const float* __restrict__ attn,
                        const int* __restrict__ idxs) {
    float* rows = (float*)sm;                    // 36*256
    int*   sc   = (int*)(sm + 36864);
    float* r0   = (float*)(sm + 37376);
    float* r1   = (float*)(sm + 37888);
    float* r2   = (float*)(sm + 38400);
    int n = bid >> 7, a = bid & 127;
    int tid = threadIdx.x;
    if (tid < cS) sc[tid] = idxs[n * cIDXW + tid];
    __syncthreads();
    int i = sc[a];
    for (int idx = tid; idx < 36 * 64; idx += 256) {
        int r = idx >> 6, c = idx & 63;
        int l = r / 12, h = r - l * 12;
        long off = ((((long)l * cN + n) * 12 + h) * cL + i) * cL;
        *(float4*)&rows[r * 256 + c * 4] = *(const float4*)(attn + off + c * 4);
    }
    __syncthreads();
    float a0 = 0.f, a1 = 0.f, a2 = 0.f;
    if (tid < cS) {
        int j = sc[tid];
#pragma unroll
        for (int h = 0; h < 12; ++h) {
            a0 += rows[h * 256 + j];
            a1 += rows[(12 + h) * 256 + j];
            a2 += rows[(24 + h) * 256 + j];
        }
        r0[tid] = a0; r1[tid] = a1; r2[tid] = a2;
    }
    __syncthreads();
    for (int st = 64; st > 0; st >>= 1) {
        if (tid < st) { r0[tid] += r0[tid + st]; r1[tid] += r1[tid + st]; r2[tid] += r2[tid + st]; }
        __syncthreads();
    }
    if (tid < cS) {
        float d0 = r0[0] * (1.f / 12.f) + 1e-9f;
        float d1 = r1[0] * (1.f / 12.f) + 1e-9f;
        float d2 = r2[0] * (1.f / 12.f) + 1e-9f;
        g_t2t[((long)(n * cS + a)) * cS + tid] =
            ((a0 * (1.f / 12.f)) / d0 + (a1 * (1.f / 12.f)) / d1 +
             (a2 * (1.f / 12.f)) / d2) * (1.f / 3.f);
    }
}

// ---- convW: W1 blocks {0,3,4,1,5,2} -> tiled swizzled bf16 ----
__device__ void dev_convW(char* sm, int bid, const float* __restrict__ W1) {
    float (*tile)[33] = (float(*)[33])sm;
    int bx = bid % 24, by = (bid / 24) % 24, blk = bid / 576;  // 0..5
    const int map[6] = {0, 3, 4, 1, 5, 2};
    int wb = map[blk];
    int tid = threadIdx.x, tx = tid & 31, ty = tid >> 5;
    const float* src = W1 + (long)wb * cD * cNH;
    int k0 = by * 32, n0 = bx * 32;
#pragma unroll
    for (int j = 0; j < 4; ++j)
        tile[ty + j * 8][tx] = src[(long)(k0 + ty + j * 8) * cNH + n0 + tx];
    __syncthreads();
#pragma unroll
    for (int j = 0; j < 4; ++j) {
        int nIdx = n0 + ty + j * 8, kIdx = k0 + tx;
        long off = (((long)(blk * 6 + (nIdx >> 7)) * 12 + (kIdx >> 6)) * 128 +
                    (nIdx & 127)) * 128 +
                   (((kIdx & 63) * 2) ^ ((nIdx & 7) << 4));
        *(__nv_bfloat16*)((char*)g_Btil + off) = __float2bfloat16_rn(tile[tx][ty + j * 8]);
    }
}

// ---- argsmall (+ bf16 tiled argemb/u2u) ----
__device__ __forceinline__ void st_a4(int chunk, int m, int d, float v) {
    int mt = m >> 7, r = m & 127;
    long off = (((long)(chunk * 2 + mt) * 12 + (d >> 6)) * 128 + r) * 128 +
               (((d & 63) * 2) ^ ((r & 7) << 4));
    *(__nv_bfloat16*)((char*)g_Atil4 + off) = __float2bfloat16_rn(v);
}
__device__ void dev_argsmall(char* sm, int n, const float* __restrict__ argw) {
    float* s_ae  = (float*)sm;
    float* s_aw  = (float*)(sm + 27648);
    float* s_dot = (float*)(sm + 27984);
    float* s_a2a = (float*)(sm + 28320);
    int tid = threadIdx.x;
    if (tid < cA * cA) s_aw[tid] = argw[n * cA * cA + tid];
    __syncthreads();
    for (int idx = tid; idx < cA * cD; idx += 256) {
        int a = idx / cD, d = idx % cD;
        float acc = 0.f;
#pragma unroll
        for (int k = 0; k < cA; ++k)
            acc += g_argraw[((long)(n * cA + k)) * cD + d] * s_aw[k * cA + a];
        s_ae[a * cD + d] = acc;
        g_argemb[((long)(n * cA + a)) * cD + d] = acc;
        st_a4(0, n * cA + a, d, acc);
    }
    __syncthreads();
    int wa = tid >> 5, lane = tid & 31;
    for (int p = wa; p < cA * cA; p += 8) {
        int a = p / cA, b = p % cA;
        float acc = 0.f;
        for (int r = lane; r < cD; r += 32) acc += s_ae[a * cD + r] * s_ae[b * cD + r];
        for (int o = 16; o > 0; o >>= 1) acc += __shfl_xor_sync(0xffffffffu, acc, o);
        if (lane == 0) s_dot[p] = acc;
    }
    __syncthreads();
    if (tid < cA) {
        float mx = -1e30f;
        for (int b = 0; b < cA; ++b) mx = fmaxf(mx, s_dot[tid * cA + b]);
        float e[cA], sum = 0.f;
        for (int b = 0; b < cA; ++b) { e[b] = expf(s_dot[tid * cA + b] - mx); sum += e[b]; }
        float inv = 1.f / sum;
        for (int b = 0; b < cA; ++b) s_a2a[tid * cA + b] = e[b] * inv;
    }
    __syncthreads();
    for (int idx = tid; idx < cA * cD; idx += 256) {
        int a = idx / cD, d = idx % cD;
        float acc = 0.f;
#pragma unroll
        for (int b = 0; b < cA; ++b) acc += s_a2a[a * cA + b] * s_ae[b * cD + d];
        g_u2u[((long)(n * cA + a)) * cD + d] = acc;
        st_a4(1, n * cA + a, d, acc);
    }
}

// ---- SIMT GEMM (reg double-buffered), roles 0/1/2 ----
template <int ROLE>
__device__ void dev_gemm(char* smraw, int bx, int by, int bz,
                         const float* __restrict__ PA) {
    constexpr bool ATRANS = (ROLE == 0 || ROLE == 1);
    constexpr int BK = 16;
    float (*As)[68]  = reinterpret_cast<float(*)[68]>(smraw);
    float (*Bs)[128] = reinterpret_cast<float(*)[128]>(smraw + BK * 68 * 4);

    const float* A = nullptr; const float* B = nullptr;
    int ldA = 0, ldB = 0, n = bz, koE = cS;
    if (ROLE == 0) { A = PA + (long)n * cS * cE; ldA = cE;
                     B = g_sent + (long)n * cS * cD; ldB = cD; }
    if (ROLE == 1) { A = PA + (long)n * cS * cE; ldA = cE;
                     B = g_t2t + (long)n * cS * cS; ldB = cS; }
    if (ROLE == 2) { A = g_X + (long)n * cE * cS; ldA = cS;
                     B = g_sent + (long)n * cS * cD; ldB = cD; }
    int m0 = bx * 64, n0 = by * 128;
    int tid = threadIdx.x, tx = tid & 15, ty = tid >> 4;

    float2 acc[4][4];
#pragma unroll
    for (int i = 0; i < 4; ++i)
#pragma unroll
        for (int p = 0; p < 4; ++p) acc[i][p] = make_float2(0.f, 0.f);

    auto ldA_t = [&](int ko) -> float4 {
        if (ATRANS) {
            int r = tid >> 4, c4 = (tid & 15) << 2;
            return *(const float4*)(A + (long)(ko + r) * ldA + m0 + c4);
        } else {
            int m = tid >> 2, kq = (tid & 3) << 2;
            return *(const float4*)(A + (long)(m0 + m) * ldA + ko + kq);
        }
    };
    auto stA = [&](float4 v) {
        if (ATRANS) {
            int r = tid >> 4, c4 = (tid & 15) << 2;
            As[r][c4] = v.x; As[r][c4 + 1] = v.y; As[r][c4 + 2] = v.z; As[r][c4 + 3] = v.w;
        } else {
            int m = tid >> 2, kq = (tid & 3) << 2;
            As[kq][m] = v.x; As[kq + 1][m] = v.y; As[kq + 2][m] = v.z; As[kq + 3][m] = v.w;
        }
    };
    auto ldB_t = [&](int ko, float4& b0, float4& b1) {
        int r = tid >> 5, c4 = (tid & 31) << 2;
        b0 = *(const float4*)(B + (long)(ko + r) * ldB + n0 + c4);
        b1 = *(const float4*)(B + (long)(ko + r + 8) * ldB + n0 + c4);
    };
    auto stB = [&](float4 b0, float4 b1) {
        int r = tid >> 5, c4 = (tid & 31) << 2;
        *(float4*)&Bs[r][c4] = b0;
        *(float4*)&Bs[r + 8][c4] = b1;
    };

    { float4 a0 = ldA_t(0); float4 b0, b1; ldB_t(0, b0, b1);
      stA(a0); stB(b0, b1); }
    __syncthreads();
    for (int ko = 0; ko < koE; ko += BK) {
        bool has = (ko + BK) < koE;
        float4 nA, nB0, nB1;
        if (has) { nA = ldA_t(ko + BK); ldB_t(ko + BK, nB0, nB1); }
#pragma unroll
        for (int kk = 0; kk < BK; ++kk) {
            float4 av = *(const float4*)&As[kk][ty << 2];
            float a_[4] = {av.x, av.y, av.z, av.w};
            float2 b_[4];
#pragma unroll
            for (int p = 0; p < 4; ++p)
                b_[p] = *(const float2*)&Bs[kk][(tx << 1) + (p << 5)];
#pragma unroll
            for (int i = 0; i < 4; ++i) {
                float2 ad = make_float2(a_[i], a_[i]);
#pragma unroll
                for (int p = 0; p < 4; ++p) fma2(acc[i][p], ad, b_[p]);
            }
        }
        __syncthreads();
        if (has) { stA(nA); stB(nB0, nB1); __syncthreads(); }
    }
#pragma unroll
    for (int i = 0; i < 4; ++i) {
        int m = m0 + (ty << 2) + i;
#pragma unroll
        for (int p = 0; p < 4; ++p) {
            int col = n0 + (tx << 1) + (p << 5);
            float2 v = acc[i][p];
            if (ROLE == 0 || ROLE == 2) {
                int chunk = (ROLE == 0) ? 0 : 1;
                long off = (((long)((chunk * 16 + n) * 12 + (col >> 6))) * 128 + m) * 128 +
                           (((col & 63) * 2) ^ ((m & 7) << 4));
                *(uint32_t*)((char*)g_Atil + off) = pkbf(v.x, v.y);
                if (ROLE == 0)
                    *(float2*)&g_ent[((long)(n * cE + m)) * cD + col] = v;
            } else {
                *(float2*)&g_X[((long)(n * cE + m)) * cS + col] = v;
            }
        }
    }
}

// ---- w2: fat blocks (argemb in smem, 4 e-rows per warp) ----
__device__ void dev_w2(char* sm, int u) {
    int n = u >> 2, eq = u & 3;
    float* s_ag = (float*)sm;                // 9*768 floats
    int tid = threadIdx.x;
    for (int i = tid; i < cA * cD; i += 256)
        s_ag[i] = g_argemb[(long)n * cA * cD + i];
    __syncthreads();
    int wid = tid >> 5, lane = tid & 31;
#pragma unroll
    for (int rr = 0; rr < 4; ++rr) {
        int e = eq * 32 + wid * 4 + rr;
        const float* er = g_ent + ((long)(n * cE + e)) * cD;
        float acc[cA];
#pragma unroll
        for (int a = 0; a < cA; ++a) acc[a] = 0.f;
        for (int r = lane; r < cD; r += 32) {
            float ev = er[r];
#pragma unroll
            for (int a = 0; a < cA; ++a) acc[a] += ev * s_ag[a * cD + r];
        }
#pragma unroll
        for (int a = 0; a < cA; ++a) {
            float v = acc[a];
            for (int o = 16; o > 0; o >>= 1) v += __shfl_xor_sync(0xffffffffu, v, o);
            if (lane == 0)
                g_w[(n * cE + e) * cA + a] = (v * 0.03608439182435161f - 5.0f) * 0.5f;
        }
    }
}

// ---- atok2: per-(n, col-chunk); STATIC accumulator indexing ---------------
__device__ void dev_atok2(char* sm, int u) {
    int n = u / 6, nt = u % 6;
    float* sw = (float*)sm;                  // 128*9 floats
    int tid = threadIdx.x;
    if (tid < cE)
#pragma unroll
        for (int a = 0; a < cA; ++a)
            sw[tid * cA + a] = g_w[(n * cE + tid) * cA + a];
    __syncthreads();
    int col = tid & 127, h = tid >> 7;
    const float* base = g_ent + (long)n * cE * cD + nt * 128 + col;
    if (h == 0) {
        // a in {0,2,4,6,8} — 5 register accumulators, static indices
        float acc[5] = {0.f, 0.f, 0.f, 0.f, 0.f};
        for (int e0 = 0; e0 < cE; e0 += 8) {
            float v[8];
#pragma unroll
            for (int j = 0; j < 8; ++j) v[j] = base[(long)(e0 + j) * cD];
#pragma unroll
            for (int j = 0; j < 8; ++j) {
                const float* swr = sw + (e0 + j) * cA;
#pragma unroll
                for (int i = 0; i < 5; ++i) acc[i] += swr[2 * i] * v[j];
            }
        }
#pragma unroll
        for (int i = 0; i < 5; ++i)
            st_a4(2, n * cA + 2 * i, nt * 128 + col, acc[i]);
    } else {
        // a in {1,3,5,7} — 4 register accumulators, static indices
        float acc[4] = {0.f, 0.f, 0.f, 0.f};
        for (int e0 = 0; e0 < cE; e0 += 8) {
            float v[8];
#pragma unroll
            for (int j = 0; j < 8; ++j) v[j] = base[(long)(e0 + j) * cD];
#pragma unroll
            for (int j = 0; j < 8; ++j) {
                const float* swr = sw + (e0 + j) * cA;
#pragma unroll
                for (int i = 0; i < 4; ++i) acc[i] += swr[2 * i + 1] * v[j];
            }
        }
#pragma unroll
        for (int i = 0; i < 4; ++i)
            st_a4(2, n * cA + 2 * i + 1, nt * 128 + col, acc[i]);
    }
}

// ---- unified HMMA pipeline: all blocks 12 iters, 3-stage bulk-copy --------
constexpr int EP_TILE  = 16384;
constexpr int EP_STG   = 2 * EP_TILE;
constexpr int EP_NST   = 3;
constexpr int EP_SMEM  = 128 + EP_NST * EP_STG;   // 98432

__device__ void dev_hmma(char* sm, int bid) {
    uint32_t smB = smem_u32(sm);
    // 0..191: epart splitK (ch=bid/96); 192..227: gemm4; 228..239: atokW4
    const char* Ab; const char* Bb; float* dst;
    bool guard = false;
    if (bid < 192) {
        int ch = bid / 96, u = bid % 96;
        int mt = u & 15, nt = u >> 4;
        Ab = (const char*)g_Atil + ((long)((ch * 16 + mt) * 12)) * EP_TILE;
        Bb = (const char*)g_Btil + ((long)((ch * 6 + nt) * 12)) * EP_TILE;
        dst = (ch ? g_Epart2 : g_Epart) + (long)(mt * 128) * cNH + nt * 128;
    } else if (bid < 228) {
        int i = bid - 192, ch = i / 12, u = i % 12;
        int mt = u / 6, nt = u % 6;
        int ach = (ch == 1) ? 1 : 0;
        Ab = (const char*)g_Atil4 + ((long)((ach * 2 + mt) * 12)) * EP_TILE;
        Bb = (const char*)g_Btil + ((long)(((3 + ch) * 6 + nt) * 12)) * EP_TILE;
        dst = g_S4 + (long)ch * SZS + (long)(mt * 128) * cNH + nt * 128;
    } else {
        int i = bid - 228, mt = i / 6, nt = i % 6;
        Ab = (const char*)g_Atil4 + ((long)((4 + mt) * 12)) * EP_TILE;
        Bb = (const char*)g_Btil + ((long)((2 * 6 + nt) * 12)) * EP_TILE;
        dst = g_AtokW4 + (long)(mt * 128) * cNH + nt * 128;
        guard = (mt == 1);                  // rows 128..255 -> only 128..143 valid
    }
    int tid = threadIdx.x, lane = tid & 31, wid = tid >> 5;
    int warpM = (wid & 3) * 32, warpN = (wid >> 2) * 64;
    int lrow = lane & 7, lsel = lane >> 3;

    if (tid == 0)
        for (int s = 0; s < EP_NST; ++s)
            asm volatile("mbarrier.init.shared.b64 [%0], 1;" :: "r"(smB + s * 8) : "memory");
    __syncthreads();

    auto issue = [&](int t, int stg) {
        uint32_t mbar = smB + stg * 8;
        uint32_t dsts = smB + 128 + stg * EP_STG;
        asm volatile("mbarrier.arrive.expect_tx.shared.b64 _, [%0], %1;"
                     :: "r"(mbar), "r"((uint32_t)EP_STG) : "memory");
        asm volatile("cp.async.bulk.shared::cta.global.mbarrier::complete_tx::bytes "
                     "[%0], [%1], %2, [%3];"
                     :: "r"(dsts), "l"(Ab + (long)t * EP_TILE),
                        "r"((uint32_t)EP_TILE), "r"(mbar) : "memory");
        asm volatile("cp.async.bulk.shared::cta.global.mbarrier::complete_tx::bytes "
                     "[%0], [%1], %2, [%3];"
                     :: "r"(dsts + EP_TILE), "l"(Bb + (long)t * EP_TILE),
                        "r"((uint32_t)EP_TILE), "r"(mbar) : "memory");
    };
    if (tid == 0) { issue(0, 0); issue(1, 1); issue(2, 2); }

    float acc[2][8][4];
#pragma unroll
    for (int mi = 0; mi < 2; ++mi)
#pragma unroll
        for (int ni = 0; ni < 8; ++ni)
#pragma unroll
            for (int c = 0; c < 4; ++c) acc[mi][ni][c] = 0.f;

    uint32_t ph[EP_NST] = {0, 0, 0};
    for (int t = 0; t < 12; ++t) {
        int stg = t % EP_NST;
        mbar_wait(smB + stg * 8, ph[stg]);
        ph[stg] ^= 1;
        uint32_t aS = smB + 128 + stg * EP_STG, bS = aS + EP_TILE;
#pragma unroll
        for (int ks = 0; ks < 64; ks += 16) {
            uint32_t kbyte = (uint32_t)(ks * 2 + ((lsel >> 1) << 4));
            uint32_t afr[2][4], bfr[4][4];
#pragma unroll
            for (int mi = 0; mi < 2; ++mi) {
                int row = warpM + mi * 16 + lrow + ((lsel & 1) << 3);
                ldsm4(afr[mi], aS + row * 128 + (kbyte ^ ((row & 7) << 4)));
            }
#pragma unroll
            for (int g = 0; g < 4; ++g) {
                int row = warpN + g * 16 + lrow + ((lsel & 1) << 3);
                ldsm4(bfr[g], bS + row * 128 + (kbyte ^ ((row & 7) << 4)));
            }
#pragma unroll
            for (int g = 0; g < 4; ++g) {
                mma16816(acc[0][2 * g],     afr[0], bfr[g][0], bfr[g][2]);
                mma16816(acc[0][2 * g + 1], afr[0], bfr[g][1], bfr[g][3]);
                mma16816(acc[1][2 * g],     afr[1], bfr[g][0], bfr[g][2]);
                mma16816(acc[1][2 * g + 1], afr[1], bfr[g][1], bfr[g][3]);
            }
        }
        __syncthreads();
        if (t + EP_NST < 12 && tid == 0) issue(t + EP_NST, stg);
    }

#pragma unroll
    for (int mi = 0; mi < 2; ++mi)
#pragma unroll
        for (int ni = 0; ni < 8; ++ni) {
            int r = warpM + mi * 16 + (lane >> 2);
            int c = warpN + ni * 8 + (lane & 3) * 2;
            if (!guard || r < 16)
                *(float2*)&dst[(long)r * cNH + c] =
                    make_float2(acc[mi][ni][0], acc[mi][ni][1]);
            if (!guard || r + 8 < 16)
                *(float2*)&dst[(long)(r + 8) * cNH + c] =
                    make_float2(acc[mi][ni][2], acc[mi][ni][3]);
        }
}

// ---- final ----
__device__ void dev_final(char* sm, int bid,
                          const float* __restrict__ b1, const float* __restrict__ W2,
                          const float* __restrict__ b2, const int* __restrict__ argmap,
                          float* __restrict__ out) {
    float* sEp    = (float*)sm;
    float* sw9    = (float*)(sm + 3072);
    float* sScore = (float*)(sm + 3136);
    int n = bid >> 7, e = bid & 127;
    int tid = threadIdx.x;
    if (tid < cA) sw9[tid] = g_w[(n * cE + e) * cA + tid];
    __syncthreads();
    const float* Y2b = g_S4 + 2L * SZS;
    for (int r = tid; r < cNH; r += 256) {
        long ro = ((long)(n * cE + e)) * cNH + r;
        float s = g_Epart[ro] + g_Epart2[ro] + b1[r];
#pragma unroll
        for (int a = 0; a < cA; ++a) s += sw9[a] * Y2b[((long)(n * cA + a)) * cNH + r];
        sEp[r] = s;
    }
    __syncthreads();
    int wid = tid >> 5, lane = tid & 31;
    for (int a = wid; a < cA; a += 8) {
        long rowoff = ((long)(n * cA + a)) * cNH;
        const float* ap0 = g_S4 + rowoff;
        const float* ap1 = g_S4 + SZS + rowoff;
        const float* apL = g_AtokW4 + rowoff;
        float acc = 0.f;
        for (int r = lane; r < cNH; r += 32) {
            float pre = sEp[r] + ap0[r] + ap1[r] + apL[r];
            float hv = 0.5f * pre * (1.0f + erff(pre * 0.7071067811865476f));
            acc += hv * W2[r];
        }
        for (int o = 16; o > 0; o >>= 1) acc += __shfl_xor_sync(0xffffffffu, acc, o);
        if (lane == 0) sScore[a] = acc + b2[0];
    }
    __syncthreads();
    if (tid < cROLES) {
        float v = -1000000.0f;
#pragma unroll
        for (int a = 0; a < cA; ++a)
            if (argmap[n * cA + a] == tid) v = sScore[a];
        out[((long)(n * cE + e)) * cROLES + tid] = v;
    }
}

// ======================= phase kernels ======================================
__global__ void __launch_bounds__(256, 1) k_p1(const float* attn, const float* emb,
                                               const int* idxs, const float* W1) {
    extern __shared__ char sm[];
    int b = blockIdx.x;
    if (b < 2048) dev_t2t(sm, b, attn, idxs);
    else if (b < 4240) dev_gather(b - 2048, emb, idxs);
    else dev_convW(sm, b - 4240, W1);
}
__global__ void __launch_bounds__(256, 1) k_p2(const float* em, const float* argw) {
    extern __shared__ char sm[];
    int b = blockIdx.x;
    if (b < 192)      dev_gemm<0>(sm, b & 1, (b >> 1) % 6, b / 12, em);
    else if (b < 224) { int i = b - 192; dev_gemm<1>(sm, i & 1, 0, i >> 1, em); }
    else              dev_argsmall(sm, b - 224, argw);
}
// p3: gemm2(192) + w2(64)
__global__ void __launch_bounds__(256, 1) k_p3() {
    extern __shared__ char sm[];
    int b = blockIdx.x;
    if (b < 192) dev_gemm<2>(sm, b & 1, (b >> 1) % 6, b / 12, nullptr);
    else         dev_w2(sm, b - 192);
}
// p4a: atok2 (needs w from p3), 96 blocks
__global__ void __launch_bounds__(256, 1) k_p4a() {
    extern __shared__ char sm[];
    dev_atok2(sm, blockIdx.x);
}
// p4b: 240 uniform 12-iter HMMA blocks
__global__ void __launch_bounds__(256, 1) k_p4b() {
    extern __shared__ char sm[];
    dev_hmma(sm, blockIdx.x);
}
__global__ void __launch_bounds__(256, 1) k_p5(const float* b1, const float* W2,
                                               const float* b2, const int* argmap,
                                               float* out) {
    extern __shared__ char sm[];
    dev_final(sm, blockIdx.x, b1, W2, b2, argmap, out);
}

// ---------------- launch ----------------------------------------------------
extern "C" void kernel_launch(void* const* d_in, const int* in_sizes, int n_in,
                              void* d_out, int out_size) {
    const float* emb  = (const float*)d_in[0];
    const float* attn = (const float*)d_in[1];
    const float* em   = (const float*)d_in[2];
    const float* argw = (const float*)d_in[3];
    const float* W1   = (const float*)d_in[5];
    const float* b1   = (const float*)d_in[6];
    const float* W2   = (const float*)d_in[7];
    const float* b2   = (const float*)d_in[8];
    const int*   idxs = (const int*)d_in[9];
    const int*   amap = (const int*)d_in[10];
    float* out = (float*)d_out;

    cudaFuncSetAttribute(k_p4b, cudaFuncAttributeMaxDynamicSharedMemorySize, EP_SMEM);

    k_p1 <<<7696, 256, 38912>>>(attn, emb, idxs, W1);
    k_p2 <<<240,  256, 28656>>>(em, argw);
    k_p3 <<<256,  256, 27648>>>();
    k_p4a<<<96,   256, 4608>>>();
    k_p4b<<<240,  256, EP_SMEM>>>();
    k_p5 <<<2048, 256, 3200>>>(b1, W2, b2, amap, out);
}

// round 16
// speedup vs baseline: 1.3888x; 1.0075x over previous
#include <cuda_runtime.h>
#include <cuda_bf16.h>
#include <cstdint>

constexpr int cN  = 16, cL = 256, cS = 128, cE = 128, cA = 9;
constexpr int cD  = 768, cNH = 768, cIDXW = 130, cROLES = 24;
constexpr int cM  = cN * cA;            // 144
constexpr int SZS = 256 * cNH;          // padded slice rows

// ---------------- scratch ---------------------------------------------------
__device__ float g_sent   [cN * cS * cD];
__device__ float g_argraw [cN * cA * cD];
__device__ float g_argemb [cN * cA * cD];
__device__ float g_u2u    [cN * cA * cD];
__device__ float g_t2t    [cN * cS * cS];
__device__ float g_ent    [cN * cE * cD];
__device__ float g_X      [cN * cE * cS];
__device__ float g_w      [cN * cE * cA];
__device__ float g_Epart  [cN * cE * cNH];
__device__ float g_Epart2 [cN * cE * cNH];
__device__ float g_S4     [3 * SZS];       // argemb@W1, u2u@W5, argemb@W2 (padded)
__device__ float g_AtokW4 [cM * cNH];
__device__ __nv_bfloat16 g_Atil [2 * cN * cE * cD];  // tiled bf16 {ent, Ah2h}
__device__ __nv_bfloat16 g_Atil4[3 * 256 * cD];      // tiled bf16 {argemb, u2u, atok}
__device__ __nv_bfloat16 g_Btil [6 * cNH * cD];      // tiled bf16 W {0,3,4,1,5,2}

// ---------------- helpers ---------------------------------------------------
__device__ __forceinline__ void fma2(float2& d, float2 a, float2 b) {
    asm("fma.rn.f32x2 %0, %1, %2, %0;"
        : "+l"(reinterpret_cast<unsigned long long&>(d))
        : "l"(reinterpret_cast<unsigned long long&>(a)),
          "l"(reinterpret_cast<unsigned long long&>(b)));
}
__device__ __forceinline__ uint32_t smem_u32(const void* p) {
    return (uint32_t)__cvta_generic_to_shared(p);
}
__device__ __forceinline__ uint32_t pkbf(float a, float b) {
    __nv_bfloat162 h = __floats2bfloat162_rn(a, b);
    return *reinterpret_cast<uint32_t*>(&h);
}
__device__ __forceinline__ void ldsm4(uint32_t* r, uint32_t addr) {
    asm volatile("ldmatrix.sync.aligned.m8n8.x4.shared.b16 {%0,%1,%2,%3}, [%4];"
        : "=r"(r[0]), "=r"(r[1]), "=r"(r[2]), "=r"(r[3]) : "r"(addr));
}
__device__ __forceinline__ void mma16816(float* c, const uint32_t* a,
                                         uint32_t b0, uint32_t b1) {
    asm volatile(
        "mma.sync.aligned.m16n8k16.row.col.f32.bf16.bf16.f32 "
        "{%0,%1,%2,%3}, {%4,%5,%6,%7}, {%8,%9}, {%0,%1,%2,%3};"
        : "+f"(c[0]), "+f"(c[1]), "+f"(c[2]), "+f"(c[3])
        : "r"(a[0]), "r"(a[1]), "r"(a[2]), "r"(a[3]), "r"(b0), "r"(b1));
}
__device__ __forceinline__ void mbar_wait(uint32_t mbar, uint32_t parity) {
    uint32_t done;
    asm volatile("{\n\t.reg .pred p;\n\t"
        "mbarrier.try_wait.parity.acquire.cta.shared::cta.b64 p, [%1], %2;\n\t"
        "selp.b32 %0, 1, 0, p;\n\t}" : "=r"(done) : "r"(mbar), "r"(parity) : "memory");
    while (!done)
        asm volatile("{\n\t.reg .pred p;\n\t"
            "mbarrier.try_wait.parity.acquire.cta.shared::cta.b64 p, [%1], %2, 0x989680;\n\t"
            "selp.b32 %0, 1, 0, p;\n\t}" : "=r"(done) : "r"(mbar), "r"(parity) : "memory");
}

// ======================= role device functions ==============================

// ---- gather ----
__device__ void dev_gather(int row, const float* __restrict__ emb,
                           const int* __restrict__ idxs) {
    int tid = threadIdx.x;
    if (tid >= 192) return;
    if (row < cN * cS) {
        int n = row >> 7, s = row & 127;
        int src = idxs[n * cIDXW + s];
        ((float4*)(g_sent + (long)row * cD))[tid] =
            ((const float4*)(emb + ((long)n * cL + src) * cD))[tid];
    } else {
        int r = row - cN * cS, n = r / cA, a = r % cA;
        int src = idxs[n * cIDXW + cS] + 1 + a;
        ((float4*)(g_argraw + (long)r * cD))[tid] =
            ((const float4*)(emb + ((long)n * cL + src) * cD))[tid];
    }
}

// ---- t2t ----
__device__ void dev_t2t(char* sm, int bid, const float* __restrict__ attn,
                        const int* __restrict__ idxs) {
    float* rows = (float*)sm;                    // 36*256
    int*   sc   = (int*)(sm + 36864);
    float* r0   = (float*)(sm + 37376);
    float* r1   = (float*)(sm + 37888);
    float* r2   = (float*)(sm + 38400);
    int n = bid >> 7, a = bid & 127;
    int tid = threadIdx.x;
    if (tid < cS) sc[tid] = idxs[n * cIDXW + tid];
    __syncthreads();
    int i = sc[a];
    for (int idx = tid; idx < 36 * 64; idx += 256) {
        int r = idx >> 6, c = idx & 63;
        int l = r / 12, h = r - l * 12;
        long off = ((((long)l * cN + n) * 12 + h) * cL + i) * cL;
        *(float4*)&rows[r * 256 + c * 4] = *(const float4*)(attn + off + c * 4);
    }
    __syncthreads();
    float a0 = 0.f, a1 = 0.f, a2 = 0.f;
    if (tid < cS) {
        int j = sc[tid];
#pragma unroll
        for (int h = 0; h < 12; ++h) {
            a0 += rows[h * 256 + j];
            a1 += rows[(12 + h) * 256 + j];
            a2 += rows[(24 + h) * 256 + j];
        }
        r0[tid] = a0; r1[tid] = a1; r2[tid] = a2;
    }
    __syncthreads();
    for (int st = 64; st > 0; st >>= 1) {
        if (tid < st) { r0[tid] += r0[tid + st]; r1[tid] += r1[tid + st]; r2[tid] += r2[tid + st]; }
        __syncthreads();
    }
    if (tid < cS) {
        float d0 = r0[0] * (1.f / 12.f) + 1e-9f;
        float d1 = r1[0] * (1.f / 12.f) + 1e-9f;
        float d2 = r2[0] * (1.f / 12.f) + 1e-9f;
        g_t2t[((long)(n * cS + a)) * cS + tid] =
            ((a0 * (1.f / 12.f)) / d0 + (a1 * (1.f / 12.f)) / d1 +
             (a2 * (1.f / 12.f)) / d2) * (1.f / 3.f);
    }
}

// ---- convW: W1 blocks {0,3,4,1,5,2} -> tiled swizzled bf16 ----
__device__ void dev_convW(char* sm, int bid, const float* __restrict__ W1) {
    float (*tile)[33] = (float(*)[33])sm;
    int bx = bid % 24, by = (bid / 24) % 24, blk = bid / 576;  // 0..5
    const int map[6] = {0, 3, 4, 1, 5, 2};
    int wb = map[blk];
    int tid = threadIdx.x, tx = tid & 31, ty = tid >> 5;
    const float* src = W1 + (long)wb * cD * cNH;
    int k0 = by * 32, n0 = bx * 32;
#pragma unroll
    for (int j = 0; j < 4; ++j)
        tile[ty + j * 8][tx] = src[(long)(k0 + ty + j * 8) * cNH + n0 + tx];
    __syncthreads();
#pragma unroll
    for (int j = 0; j < 4; ++j) {
        int nIdx = n0 + ty + j * 8, kIdx = k0 + tx;
        long off = (((long)(blk * 6 + (nIdx >> 7)) * 12 + (kIdx >> 6)) * 128 +
                    (nIdx & 127)) * 128 +
                   (((kIdx & 63) * 2) ^ ((nIdx & 7) << 4));
        *(__nv_bfloat16*)((char*)g_Btil + off) = __float2bfloat16_rn(tile[tx][ty + j * 8]);
    }
}

// ---- argsmall (+ bf16 tiled argemb/u2u) ----
__device__ __forceinline__ void st_a4(int chunk, int m, int d, float v) {
    int mt = m >> 7, r = m & 127;
    long off = (((long)(chunk * 2 + mt) * 12 + (d >> 6)) * 128 + r) * 128 +
               (((d & 63) * 2) ^ ((r & 7) << 4));
    *(__nv_bfloat16*)((char*)g_Atil4 + off) = __float2bfloat16_rn(v);
}
__device__ void dev_argsmall(char* sm, int n, const float* __restrict__ argw) {
    float* s_ae  = (float*)sm;
    float* s_aw  = (float*)(sm + 27648);
    float* s_dot = (float*)(sm + 27984);
    float* s_a2a = (float*)(sm + 28320);
    int tid = threadIdx.x;
    if (tid < cA * cA) s_aw[tid] = argw[n * cA * cA + tid];
    __syncthreads();
    for (int idx = tid; idx < cA * cD; idx += 256) {
        int a = idx / cD, d = idx % cD;
        float acc = 0.f;
#pragma unroll
        for (int k = 0; k < cA; ++k)
            acc += g_argraw[((long)(n * cA + k)) * cD + d] * s_aw[k * cA + a];
        s_ae[a * cD + d] = acc;
        g_argemb[((long)(n * cA + a)) * cD + d] = acc;
        st_a4(0, n * cA + a, d, acc);
    }
    __syncthreads();
    int wa = tid >> 5, lane = tid & 31;
    for (int p = wa; p < cA * cA; p += 8) {
        int a = p / cA, b = p % cA;
        float acc = 0.f;
        for (int r = lane; r < cD; r += 32) acc += s_ae[a * cD + r] * s_ae[b * cD + r];
        for (int o = 16; o > 0; o >>= 1) acc += __shfl_xor_sync(0xffffffffu, acc, o);
        if (lane == 0) s_dot[p] = acc;
    }
    __syncthreads();
    if (tid < cA) {
        float mx = -1e30f;
        for (int b = 0; b < cA; ++b) mx = fmaxf(mx, s_dot[tid * cA + b]);
        float e[cA], sum = 0.f;
        for (int b = 0; b < cA; ++b) { e[b] = expf(s_dot[tid * cA + b] - mx); sum += e[b]; }
        float inv = 1.f / sum;
        for (int b = 0; b < cA; ++b) s_a2a[tid * cA + b] = e[b] * inv;
    }
    __syncthreads();
    for (int idx = tid; idx < cA * cD; idx += 256) {
        int a = idx / cD, d = idx % cD;
        float acc = 0.f;
#pragma unroll
        for (int b = 0; b < cA; ++b) acc += s_a2a[a * cA + b] * s_ae[b * cD + d];
        g_u2u[((long)(n * cA + a)) * cD + d] = acc;
        st_a4(1, n * cA + a, d, acc);
    }
}

// ---- SIMT GEMM (reg double-buffered), roles 0/1/2 ----
template <int ROLE>
__device__ void dev_gemm(char* smraw, int bx, int by, int bz,
                         const float* __restrict__ PA) {
    constexpr bool ATRANS = (ROLE == 0 || ROLE == 1);
    constexpr int BK = 16;
    float (*As)[68]  = reinterpret_cast<float(*)[68]>(smraw);
    float (*Bs)[128] = reinterpret_cast<float(*)[128]>(smraw + BK * 68 * 4);

    const float* A = nullptr; const float* B = nullptr;
    int ldA = 0, ldB = 0, n = bz, koE = cS;
    if (ROLE == 0) { A = PA + (long)n * cS * cE; ldA = cE;
                     B = g_sent + (long)n * cS * cD; ldB = cD; }
    if (ROLE == 1) { A = PA + (long)n * cS * cE; ldA = cE;
                     B = g_t2t + (long)n * cS * cS; ldB = cS; }
    if (ROLE == 2) { A = g_X + (long)n * cE * cS; ldA = cS;
                     B = g_sent + (long)n * cS * cD; ldB = cD; }
    int m0 = bx * 64, n0 = by * 128;
    int tid = threadIdx.x, tx = tid & 15, ty = tid >> 4;

    float2 acc[4][4];
#pragma unroll
    for (int i = 0; i < 4; ++i)
#pragma unroll
        for (int p = 0; p < 4; ++p) acc[i][p] = make_float2(0.f, 0.f);

    auto ldA_t = [&](int ko) -> float4 {
        if (ATRANS) {
            int r = tid >> 4, c4 = (tid & 15) << 2;
            return *(const float4*)(A + (long)(ko + r) * ldA + m0 + c4);
        } else {
            int m = tid >> 2, kq = (tid & 3) << 2;
            return *(const float4*)(A + (long)(m0 + m) * ldA + ko + kq);
        }
    };
    auto stA = [&](float4 v) {
        if (ATRANS) {
            int r = tid >> 4, c4 = (tid & 15) << 2;
            As[r][c4] = v.x; As[r][c4 + 1] = v.y; As[r][c4 + 2] = v.z; As[r][c4 + 3] = v.w;
        } else {
            int m = tid >> 2, kq = (tid & 3) << 2;
            As[kq][m] = v.x; As[kq + 1][m] = v.y; As[kq + 2][m] = v.z; As[kq + 3][m] = v.w;
        }
    };
    auto ldB_t = [&](int ko, float4& b0, float4& b1) {
        int r = tid >> 5, c4 = (tid & 31) << 2;
        b0 = *(const float4*)(B + (long)(ko + r) * ldB + n0 + c4);
        b1 = *(const float4*)(B + (long)(ko + r + 8) * ldB + n0 + c4);
    };
    auto stB = [&](float4 b0, float4 b1) {
        int r = tid >> 5, c4 = (tid & 31) << 2;
        *(float4*)&Bs[r][c4] = b0;
        *(float4*)&Bs[r + 8][c4] = b1;
    };

    { float4 a0 = ldA_t(0); float4 b0, b1; ldB_t(0, b0, b1);
      stA(a0); stB(b0, b1); }
    __syncthreads();
    for (int ko = 0; ko < koE; ko += BK) {
        bool has = (ko + BK) < koE;
        float4 nA, nB0, nB1;
        if (has) { nA = ldA_t(ko + BK); ldB_t(ko + BK, nB0, nB1); }
#pragma unroll
        for (int kk = 0; kk < BK; ++kk) {
            float4 av = *(const float4*)&As[kk][ty << 2];
            float a_[4] = {av.x, av.y, av.z, av.w};
            float2 b_[4];
#pragma unroll
            for (int p = 0; p < 4; ++p)
                b_[p] = *(const float2*)&Bs[kk][(tx << 1) + (p << 5)];
#pragma unroll
            for (int i = 0; i < 4; ++i) {
                float2 ad = make_float2(a_[i], a_[i]);
#pragma unroll
                for (int p = 0; p < 4; ++p) fma2(acc[i][p], ad, b_[p]);
            }
        }
        __syncthreads();
        if (has) { stA(nA); stB(nB0, nB1); __syncthreads(); }
    }
#pragma unroll
    for (int i = 0; i < 4; ++i) {
        int m = m0 + (ty << 2) + i;
#pragma unroll
        for (int p = 0; p < 4; ++p) {
            int col = n0 + (tx << 1) + (p << 5);
            float2 v = acc[i][p];
            if (ROLE == 0 || ROLE == 2) {
                int chunk = (ROLE == 0) ? 0 : 1;
                long off = (((long)((chunk * 16 + n) * 12 + (col >> 6))) * 128 + m) * 128 +
                           (((col & 63) * 2) ^ ((m & 7) << 4));
                *(uint32_t*)((char*)g_Atil + off) = pkbf(v.x, v.y);
                if (ROLE == 0)
                    *(float2*)&g_ent[((long)(n * cE + m)) * cD + col] = v;
            } else {
                *(float2*)&g_X[((long)(n * cE + m)) * cS + col] = v;
            }
        }
    }
}

// ---- w2: fat blocks (argemb in smem, 4 e-rows per warp) ----
__device__ void dev_w2(char* sm, int u) {
    int n = u >> 2, eq = u & 3;
    float* s_ag = (float*)sm;                // 9*768 floats
    int tid = threadIdx.x;
    for (int i = tid; i < cA * cD; i += 256)
        s_ag[i] = g_argemb[(long)n * cA * cD + i];
    __syncthreads();
    int wid = tid >> 5, lane = tid & 31;
#pragma unroll
    for (int rr = 0; rr < 4; ++rr) {
        int e = eq * 32 + wid * 4 + rr;
        const float* er = g_ent + ((long)(n * cE + e)) * cD;
        float acc[cA];
#pragma unroll
        for (int a = 0; a < cA; ++a) acc[a] = 0.f;
        for (int r = lane; r < cD; r += 32) {
            float ev = er[r];
#pragma unroll
            for (int a = 0; a < cA; ++a) acc[a] += ev * s_ag[a * cD + r];
        }
#pragma unroll
        for (int a = 0; a < cA; ++a) {
            float v = acc[a];
            for (int o = 16; o > 0; o >>= 1) v += __shfl_xor_sync(0xffffffffu, v, o);
            if (lane == 0)
                g_w[(n * cE + e) * cA + a] = (v * 0.03608439182435161f - 5.0f) * 0.5f;
        }
    }
}

// ---- atok2: static accumulators + software-pipelined load batches ---------
__device__ void dev_atok2(char* sm, int u) {
    int n = u / 6, nt = u % 6;
    float* sw = (float*)sm;                  // 128*9 floats
    int tid = threadIdx.x;
    if (tid < cE)
#pragma unroll
        for (int a = 0; a < cA; ++a)
            sw[tid * cA + a] = g_w[(n * cE + tid) * cA + a];
    __syncthreads();
    int col = tid & 127, h = tid >> 7;
    const float* base = g_ent + (long)n * cE * cD + nt * 128 + col;
    float v[8], vn[8];
#pragma unroll
    for (int j = 0; j < 8; ++j) v[j] = base[(long)j * cD];
    if (h == 0) {
        float acc[5] = {0.f, 0.f, 0.f, 0.f, 0.f};
        for (int e0 = 0; e0 < cE; e0 += 8) {
            if (e0 + 8 < cE) {
#pragma unroll
                for (int j = 0; j < 8; ++j) vn[j] = base[(long)(e0 + 8 + j) * cD];
            }
#pragma unroll
            for (int j = 0; j < 8; ++j) {
                const float* swr = sw + (e0 + j) * cA;
#pragma unroll
                for (int i = 0; i < 5; ++i) acc[i] += swr[2 * i] * v[j];
            }
#pragma unroll
            for (int j = 0; j < 8; ++j) v[j] = vn[j];
        }
#pragma unroll
        for (int i = 0; i < 5; ++i)
            st_a4(2, n * cA + 2 * i, nt * 128 + col, acc[i]);
    } else {
        float acc[4] = {0.f, 0.f, 0.f, 0.f};
        for (int e0 = 0; e0 < cE; e0 += 8) {
            if (e0 + 8 < cE) {
#pragma unroll
                for (int j = 0; j < 8; ++j) vn[j] = base[(long)(e0 + 8 + j) * cD];
            }
#pragma unroll
            for (int j = 0; j < 8; ++j) {
                const float* swr = sw + (e0 + j) * cA;
#pragma unroll
                for (int i = 0; i < 4; ++i) acc[i] += swr[2 * i + 1] * v[j];
            }
#pragma unroll
            for (int j = 0; j < 8; ++j) v[j] = vn[j];
        }
#pragma unroll
        for (int i = 0; i < 4; ++i)
            st_a4(2, n * cA + 2 * i + 1, nt * 128 + col, acc[i]);
    }
}

// ---- unified HMMA pipeline: all blocks 12 iters, 3-stage bulk-copy --------
constexpr int EP_TILE  = 16384;
constexpr int EP_STG   = 2 * EP_TILE;
constexpr int EP_NST   = 3;
constexpr int EP_SMEM  = 128 + EP_NST * EP_STG;   // 98432

__device__ void dev_hmma(char* sm, int bid) {
    uint32_t smB = smem_u32(sm);
    // 0..191: epart splitK (ch=bid/96); 192..227: gemm4; 228..239: atokW4
    const char* Ab; const char* Bb; float* dst;
    bool guard = false;
    if (bid < 192) {
        int ch = bid / 96, u = bid % 96;
        int mt = u & 15, nt = u >> 4;
        Ab = (const char*)g_Atil + ((long)((ch * 16 + mt) * 12)) * EP_TILE;
        Bb = (const char*)g_Btil + ((long)((ch * 6 + nt) * 12)) * EP_TILE;
        dst = (ch ? g_Epart2 : g_Epart) + (long)(mt * 128) * cNH + nt * 128;
    } else if (bid < 228) {
        int i = bid - 192, ch = i / 12, u = i % 12;
        int mt = u / 6, nt = u % 6;
        int ach = (ch == 1) ? 1 : 0;
        Ab = (const char*)g_Atil4 + ((long)((ach * 2 + mt) * 12)) * EP_TILE;
        Bb = (const char*)g_Btil + ((long)(((3 + ch) * 6 + nt) * 12)) * EP_TILE;
        dst = g_S4 + (long)ch * SZS + (long)(mt * 128) * cNH + nt * 128;
    } else {
        int i = bid - 228, mt = i / 6, nt = i % 6;
        Ab = (const char*)g_Atil4 + ((long)((4 + mt) * 12)) * EP_TILE;
        Bb = (const char*)g_Btil + ((long)((2 * 6 + nt) * 12)) * EP_TILE;
        dst = g_AtokW4 + (long)(mt * 128) * cNH + nt * 128;
        guard = (mt == 1);                  // rows 128..255 -> only 128..143 valid
    }
    int tid = threadIdx.x, lane = tid & 31, wid = tid >> 5;
    int warpM = (wid & 3) * 32, warpN = (wid >> 2) * 64;
    int lrow = lane & 7, lsel = lane >> 3;

    if (tid == 0)
        for (int s = 0; s < EP_NST; ++s)
            asm volatile("mbarrier.init.shared.b64 [%0], 1;" :: "r"(smB + s * 8) : "memory");
    __syncthreads();

    auto issue = [&](int t, int stg) {
        uint32_t mbar = smB + stg * 8;
        uint32_t dsts = smB + 128 + stg * EP_STG;
        asm volatile("mbarrier.arrive.expect_tx.shared.b64 _, [%0], %1;"
                     :: "r"(mbar), "r"((uint32_t)EP_STG) : "memory");
        asm volatile("cp.async.bulk.shared::cta.global.mbarrier::complete_tx::bytes "
                     "[%0], [%1], %2, [%3];"
                     :: "r"(dsts), "l"(Ab + (long)t * EP_TILE),
                        "r"((uint32_t)EP_TILE), "r"(mbar) : "memory");
        asm volatile("cp.async.bulk.shared::cta.global.mbarrier::complete_tx::bytes "
                     "[%0], [%1], %2, [%3];"
                     :: "r"(dsts + EP_TILE), "l"(Bb + (long)t * EP_TILE),
                        "r"((uint32_t)EP_TILE), "r"(mbar) : "memory");
    };
    if (tid == 0) { issue(0, 0); issue(1, 1); issue(2, 2); }

    float acc[2][8][4];
#pragma unroll
    for (int mi = 0; mi < 2; ++mi)
#pragma unroll
        for (int ni = 0; ni < 8; ++ni)
#pragma unroll
            for (int c = 0; c < 4; ++c) acc[mi][ni][c] = 0.f;

    uint32_t ph[EP_NST] = {0, 0, 0};
    for (int t = 0; t < 12; ++t) {
        int stg = t % EP_NST;
        mbar_wait(smB + stg * 8, ph[stg]);
        ph[stg] ^= 1;
        uint32_t aS = smB + 128 + stg * EP_STG, bS = aS + EP_TILE;
#pragma unroll
        for (int ks = 0; ks < 64; ks += 16) {
            uint32_t kbyte = (uint32_t)(ks * 2 + ((lsel >> 1) << 4));
            uint32_t afr[2][4], bfr[4][4];
#pragma unroll
            for (int mi = 0; mi < 2; ++mi) {
                int row = warpM + mi * 16 + lrow + ((lsel & 1) << 3);
                ldsm4(afr[mi], aS + row * 128 + (kbyte ^ ((row & 7) << 4)));
            }
#pragma unroll
            for (int g = 0; g < 4; ++g) {
                int row = warpN + g * 16 + lrow + ((lsel & 1) << 3);
                ldsm4(bfr[g], bS + row * 128 + (kbyte ^ ((row & 7) << 4)));
            }
#pragma unroll
            for (int g = 0; g < 4; ++g) {
                mma16816(acc[0][2 * g],     afr[0], bfr[g][0], bfr[g][2]);
                mma16816(acc[0][2 * g + 1], afr[0], bfr[g][1], bfr[g][3]);
                mma16816(acc[1][2 * g],     afr[1], bfr[g][0], bfr[g][2]);
                mma16816(acc[1][2 * g + 1], afr[1], bfr[g][1], bfr[g][3]);
            }
        }
        __syncthreads();
        if (t + EP_NST < 12 && tid == 0) issue(t + EP_NST, stg);
    }

#pragma unroll
    for (int mi = 0; mi < 2; ++mi)
#pragma unroll
        for (int ni = 0; ni < 8; ++ni) {
            int r = warpM + mi * 16 + (lane >> 2);
            int c = warpN + ni * 8 + (lane & 3) * 2;
            if (!guard || r < 16)
                *(float2*)&dst[(long)r * cNH + c] =
                    make_float2(acc[mi][ni][0], acc[mi][ni][1]);
            if (!guard || r + 8 < 16)
                *(float2*)&dst[(long)(r + 8) * cNH + c] =
                    make_float2(acc[mi][ni][2], acc[mi][ni][3]);
        }
}

// ---- final ----
__device__ void dev_final(char* sm, int bid,
                          const float* __restrict__ b1, const float* __restrict__ W2,
                          const float* __restrict__ b2, const int* __restrict__ argmap,
                          float* __restrict__ out) {
    float* sEp    = (float*)sm;
    float* sw9    = (float*)(sm + 3072);
    float* sScore = (float*)(sm + 3136);
    int n = bid >> 7, e = bid & 127;
    int tid = threadIdx.x;
    if (tid < cA) sw9[tid] = g_w[(n * cE + e) * cA + tid];
    __syncthreads();
    const float* Y2b = g_S4 + 2L * SZS;
    for (int r = tid; r < cNH; r += 256) {
        long ro = ((long)(n * cE + e)) * cNH + r;
        float s = g_Epart[ro] + g_Epart2[ro] + b1[r];
#pragma unroll
        for (int a = 0; a < cA; ++a) s += sw9[a] * Y2b[((long)(n * cA + a)) * cNH + r];
        sEp[r] = s;
    }
    __syncthreads();
    int wid = tid >> 5, lane = tid & 31;
    for (int a = wid; a < cA; a += 8) {
        long rowoff = ((long)(n * cA + a)) * cNH;
        const float* ap0 = g_S4 + rowoff;
        const float* ap1 = g_S4 + SZS + rowoff;
        const float* apL = g_AtokW4 + rowoff;
        float acc = 0.f;
        for (int r = lane; r < cNH; r += 32) {
            float pre = sEp[r] + ap0[r] + ap1[r] + apL[r];
            float hv = 0.5f * pre * (1.0f + erff(pre * 0.7071067811865476f));
            acc += hv * W2[r];
        }
        for (int o = 16; o > 0; o >>= 1) acc += __shfl_xor_sync(0xffffffffu, acc, o);
        if (lane == 0) sScore[a] = acc + b2[0];
    }
    __syncthreads();
    if (tid < cROLES) {
        float v = -1000000.0f;
#pragma unroll
        for (int a = 0; a < cA; ++a)
            if (argmap[n * cA + a] == tid) v = sScore[a];
        out[((long)(n * cE + e)) * cROLES + tid] = v;
    }
}

// ======================= phase kernels ======================================
__global__ void __launch_bounds__(256, 1) k_p1(const float* attn, const float* emb,
                                               const int* idxs, const float* W1) {
    extern __shared__ char sm[];
    int b = blockIdx.x;
    if (b < 2048) dev_t2t(sm, b, attn, idxs);
    else if (b < 4240) dev_gather(b - 2048, emb, idxs);
    else dev_convW(sm, b - 4240, W1);
}
__global__ void __launch_bounds__(256, 1) k_p2(const float* em, const float* argw) {
    extern __shared__ char sm[];
    int b = blockIdx.x;
    if (b < 192)      dev_gemm<0>(sm, b & 1, (b >> 1) % 6, b / 12, em);
    else if (b < 224) { int i = b - 192; dev_gemm<1>(sm, i & 1, 0, i >> 1, em); }
    else              dev_argsmall(sm, b - 224, argw);
}
// p3: gemm2(192) + w2(64)
__global__ void __launch_bounds__(256, 1) k_p3() {
    extern __shared__ char sm[];
    int b = blockIdx.x;
    if (b < 192) dev_gemm<2>(sm, b & 1, (b >> 1) % 6, b / 12, nullptr);
    else         dev_w2(sm, b - 192);
}
// p4a: atok2 (needs w from p3), 96 blocks
__global__ void __launch_bounds__(256, 1) k_p4a() {
    extern __shared__ char sm[];
    dev_atok2(sm, blockIdx.x);
}
// p4b: 240 uniform 12-iter HMMA blocks
__global__ void __launch_bounds__(256, 1) k_p4b() {
    extern __shared__ char sm[];
    dev_hmma(sm, blockIdx.x);
}
__global__ void __launch_bounds__(256, 1) k_p5(const float* b1, const float* W2,
                                               const float* b2, const int* argmap,
                                               float* out) {
    extern __shared__ char sm[];
    dev_final(sm, blockIdx.x, b1, W2, b2, argmap, out);
}

// ---------------- launch ----------------------------------------------------
extern "C" void kernel_launch(void* const* d_in, const int* in_sizes, int n_in,
                              void* d_out, int out_size) {
    const float* emb  = (const float*)d_in[0];
    const float* attn = (const float*)d_in[1];
    const float* em   = (const float*)d_in[2];
    const float* argw = (const float*)d_in[3];
    const float* W1   = (const float*)d_in[5];
    const float* b1   = (const float*)d_in[6];
    const float* W2   = (const float*)d_in[7];
    const float* b2   = (const float*)d_in[8];
    const int*   idxs = (const int*)d_in[9];
    const int*   amap = (const int*)d_in[10];
    float* out = (float*)d_out;

    cudaFuncSetAttribute(k_p4b, cudaFuncAttributeMaxDynamicSharedMemorySize, EP_SMEM);

    k_p1 <<<7696, 256, 38912>>>(attn, emb, idxs, W1);
    k_p2 <<<240,  256, 28656>>>(em, argw);
    k_p3 <<<256,  256, 27648>>>();
    k_p4a<<<96,   256, 4608>>>();
    k_p4b<<<240,  256, EP_SMEM>>>();
    k_p5 <<<2048, 256, 3200>>>(b1, W2, b2, amap, out);
}